// round 9
// baseline (speedup 1.0000x reference)
#include <cuda_runtime.h>
#include <math.h>
#include <stdint.h>

#define NN 50000      // nodes
#define NE 800000     // edges
#define NG 128        // graphs
#define FX 92         // node feature dim
#define FE 41         // edge feature dim
#define HD 64         // hidden
#define NCV 3         // conv layers
#define BN_EPS 1e-5f
#define NBLK 196      // scan blocks: 196*256 = 50176 >= NN
#define EPT 64        // edges per tile (pipelined)

typedef unsigned long long ull;
typedef long long ll;

// ---------------- device scratch ----------------
__device__ float g_h[NN * HD];
__device__ float g_acc[NN * HD];
__device__ float g_HN[NN * 4 * HD];                   // [N,256]: [f_i|s_i|f_j|s_j]
__device__ float g_Wce[NCV * FE * 2 * HD];
__device__ float g_bce[NCV * 2 * HD];
__device__ float g_Wnode[NCV * HD * 4 * HD];
__device__ float g_sum[NCV * HD];
__device__ float g_sumsq[NCV * HD];
__device__ float g_gsum[NG * HD];
__device__ float g_gcnt[NG];
// sort-by-dst machinery
__device__ int   g_deg[NN];
__device__ int   g_cursor[NN];
__device__ int   g_rp[NN];
__device__ int   g_bsum[256];
__device__ int   g_perm[NE];
__device__ int   g_srcp[NE];
__device__ int   g_dstp[NE];
__device__ float g_eap[(ll)NE * FE];   // permuted edge_attr

// ---------------- helpers ----------------
__device__ __forceinline__ ull pack2(float a, float b) {
    ull r; asm("mov.b64 %0, {%1, %2};" : "=l"(r) : "f"(a), "f"(b)); return r;
}
__device__ __forceinline__ void unpack2(ull v, float& a, float& b) {
    asm("mov.b64 {%0, %1}, %2;" : "=f"(a), "=f"(b) : "l"(v));
}
__device__ __forceinline__ void fma2(ull& d, ull a, ull b) {
    asm("fma.rn.f32x2 %0, %1, %2, %0;" : "+l"(d) : "l"(a), "l"(b));
}
// sigmoid(x) = 0.5*tanh(0.5x)+0.5  (1 MUFU)
__device__ __forceinline__ float sigmoid_f(float x) {
    float t;
    asm("tanh.approx.f32 %0, %1;" : "=f"(t) : "f"(x * 0.5f));
    return fmaf(t, 0.5f, 0.5f);
}
__device__ __forceinline__ float softplus_f(float x) {
    return fmaxf(x, 0.0f) + __logf(1.0f + __expf(-fabsf(x)));
}
__device__ __forceinline__ void red4(float* p, float4 v) {
    asm volatile("red.global.add.v4.f32 [%0], {%1,%2,%3,%4};"
                 :: "l"(p), "f"(v.x), "f"(v.y), "f"(v.z), "f"(v.w) : "memory");
}
__device__ __forceinline__ void red2(float* p, float a, float b) {
    asm volatile("red.global.add.v2.f32 [%0], {%1,%2};"
                 :: "l"(p), "f"(a), "f"(b) : "memory");
}
__device__ __forceinline__ uint32_t to_tf32(float f) {
    uint32_t r; asm("cvt.rna.tf32.f32 %0, %1;" : "=r"(r) : "f"(f)); return r;
}
__device__ __forceinline__ void mma_tf32(float c[4], uint32_t a0, uint32_t a1,
                                         uint32_t a2, uint32_t a3,
                                         uint32_t b0, uint32_t b1) {
    asm volatile(
        "mma.sync.aligned.m16n8k8.row.col.f32.tf32.tf32.f32 "
        "{%0,%1,%2,%3}, {%4,%5,%6,%7}, {%8,%9}, {%0,%1,%2,%3};"
        : "+f"(c[0]), "+f"(c[1]), "+f"(c[2]), "+f"(c[3])
        : "r"(a0), "r"(a1), "r"(a2), "r"(a3), "r"(b0), "r"(b1));
}

// ---------------- prep: fold weights ----------------
__global__ void prep_kernel(const float* __restrict__ W_emb2, const float* __restrict__ b_emb2,
                            const float* __restrict__ Wf, const float* __restrict__ bf,
                            const float* __restrict__ Ws, const float* __restrict__ bs) {
    int idx = blockIdx.x * blockDim.x + threadIdx.x;
    const int N_WCE = NCV * FE * 2 * HD;
    const int N_BCE = NCV * 2 * HD;
    const int N_WND = NCV * HD * 4 * HD;
    if (idx < N_WCE) {
        int j = idx % (2 * HD);
        int k = (idx / (2 * HD)) % FE;
        int a = idx / (2 * HD * FE);
        const float* Wb = (j < HD) ? Wf : Ws;
        int jj = j & (HD - 1);
        float s = 0.f;
        #pragma unroll 8
        for (int m = 0; m < HD; m++)
            s = fmaf(W_emb2[k * HD + m], Wb[(a * 3 * HD + 2 * HD + m) * HD + jj], s);
        g_Wce[idx] = s;
    } else if (idx < N_WCE + N_BCE) {
        int t = idx - N_WCE;
        int j = t % (2 * HD);
        int a = t / (2 * HD);
        const float* Wb = (j < HD) ? Wf : Ws;
        const float* bb = (j < HD) ? bf : bs;
        int jj = j & (HD - 1);
        float s = bb[a * HD + jj];
        #pragma unroll 8
        for (int m = 0; m < HD; m++)
            s = fmaf(b_emb2[m], Wb[(a * 3 * HD + 2 * HD + m) * HD + jj], s);
        g_bce[t] = s;
    } else if (idx < N_WCE + N_BCE + N_WND) {
        int t = idx - N_WCE - N_BCE;
        int j = t % (4 * HD);
        int m = (t / (4 * HD)) % HD;
        int a = t / (4 * HD * HD);
        int blk = j / HD;                 // 0:f_i 1:s_i 2:f_j 3:s_j
        int jj = j & (HD - 1);
        const float* Wsel = (blk & 1) ? Ws : Wf;
        int roff = (blk >= 2) ? HD : 0;
        g_Wnode[t] = Wsel[(a * 3 * HD + roff + m) * HD + jj];
    }
}

// ---------------- zero counters/stats ----------------
__global__ void zero_kernel() {
    int i = blockIdx.x * blockDim.x + threadIdx.x;
    if (i < NN) { g_deg[i] = 0; g_cursor[i] = 0; }
    if (i < NCV * HD) { g_sum[i] = 0.f; g_sumsq[i] = 0.f; }
    if (i < NG * HD) g_gsum[i] = 0.f;
    if (i < NG) g_gcnt[i] = 0.f;
}

// ---------------- sort by dst ----------------
__global__ void hist_kernel(const int* __restrict__ ei) {
    int e = blockIdx.x * blockDim.x + threadIdx.x;
    if (e < NE) atomicAdd(&g_deg[ei[NE + e]], 1);
}
__global__ void scan1_kernel() {
    __shared__ int s[256];
    int tid = threadIdx.x;
    int i = blockIdx.x * 256 + tid;
    int v = (i < NN) ? g_deg[i] : 0;
    s[tid] = v; __syncthreads();
    #pragma unroll
    for (int off = 1; off < 256; off <<= 1) {
        int t = (tid >= off) ? s[tid - off] : 0;
        __syncthreads();
        s[tid] += t;
        __syncthreads();
    }
    if (i < NN) g_rp[i] = s[tid] - v;
    if (tid == 255) g_bsum[blockIdx.x] = s[255];
}
__global__ void scan2_kernel() {
    __shared__ int s[256];
    int tid = threadIdx.x;
    int v = (tid < NBLK) ? g_bsum[tid] : 0;
    s[tid] = v; __syncthreads();
    #pragma unroll
    for (int off = 1; off < 256; off <<= 1) {
        int t = (tid >= off) ? s[tid - off] : 0;
        __syncthreads();
        s[tid] += t;
        __syncthreads();
    }
    if (tid < NBLK) g_bsum[tid] = s[tid] - v;
}
__global__ void scan3_kernel() {
    int i = blockIdx.x * 256 + threadIdx.x;
    if (i < NN) g_rp[i] += g_bsum[blockIdx.x];
}
__global__ void scatter_kernel(const int* __restrict__ ei) {
    int e = blockIdx.x * blockDim.x + threadIdx.x;
    if (e >= NE) return;
    int d = ei[NE + e];
    int s = ei[e];
    int pos = g_rp[d] + atomicAdd(&g_cursor[d], 1);
    g_perm[pos] = e;
    g_srcp[pos] = s;
    g_dstp[pos] = d;
}
__global__ void permute_ea_kernel(const float* __restrict__ ea) {
    int w = (blockIdx.x * blockDim.x + threadIdx.x) >> 5;
    int lane = threadIdx.x & 31;
    int nw = (gridDim.x * blockDim.x) >> 5;
    for (int row = w; row < NE; row += nw) {
        int e = g_perm[row];
        for (int k = lane; k < FE; k += 32)
            g_eap[(ll)row * FE + k] = ea[(ll)e * FE + k];
    }
}

// ---------------- generic fp32 GEMM with f32x2 inner loop ----------------
template <int K, int NC, int CT, int RT, int RPT>
__global__ void gemm_bias_kernel(const float* __restrict__ A, const float* __restrict__ B,
                                 const float* __restrict__ bias, float* __restrict__ C,
                                 int M, int ldb, int ldc) {
    constexpr int TR = RT * RPT;
    constexpr int KP = K + 1;
    constexpr int NT = CT * RT;
    extern __shared__ float smem[];
    float* Bs = smem;
    float* As = smem + K * NC;
    int tid = threadIdx.x;
    int tx = tid % CT;
    int ty = tid / CT;
    int c0 = blockIdx.y * NC;
    for (int i = tid; i < K * NC; i += NT) {
        int k = i / NC, c = i - k * NC;
        Bs[i] = B[k * ldb + c0 + c];
    }
    ull bp[4];
    #pragma unroll
    for (int c = 0; c < 4; c++) {
        float b0 = bias ? bias[c0 + tx * 8 + 2 * c] : 0.f;
        float b1 = bias ? bias[c0 + tx * 8 + 2 * c + 1] : 0.f;
        bp[c] = pack2(b0, b1);
    }
    for (int tile = blockIdx.x; (ll)tile * TR < M; tile += gridDim.x) {
        int row0 = tile * TR;
        __syncthreads();
        for (int i = tid; i < TR * K; i += NT) {
            int r = i / K;
            int k = i - r * K;
            int gr = row0 + r;
            As[r * KP + k] = (gr < M) ? A[(ll)gr * K + k] : 0.f;
        }
        __syncthreads();
        ull acc[RPT][4];
        #pragma unroll
        for (int r = 0; r < RPT; r++)
            #pragma unroll
            for (int c = 0; c < 4; c++) acc[r][c] = bp[c];
        for (int k = 0; k < K; k++) {
            float4 b0 = *reinterpret_cast<const float4*>(&Bs[k * NC + tx * 8]);
            float4 b1 = *reinterpret_cast<const float4*>(&Bs[k * NC + tx * 8 + 4]);
            ull p0 = pack2(b0.x, b0.y), p1 = pack2(b0.z, b0.w);
            ull p2 = pack2(b1.x, b1.y), p3 = pack2(b1.z, b1.w);
            #pragma unroll
            for (int r = 0; r < RPT; r++) {
                float a = As[(ty * RPT + r) * KP + k];
                ull ad = pack2(a, a);
                fma2(acc[r][0], ad, p0);
                fma2(acc[r][1], ad, p1);
                fma2(acc[r][2], ad, p2);
                fma2(acc[r][3], ad, p3);
            }
        }
        #pragma unroll
        for (int r = 0; r < RPT; r++) {
            int gr = row0 + ty * RPT + r;
            if (gr < M) {
                float o[8];
                #pragma unroll
                for (int c = 0; c < 4; c++) unpack2(acc[r][c], o[2 * c], o[2 * c + 1]);
                float* cp = &C[(ll)gr * ldc + c0 + tx * 8];
                *reinterpret_cast<float4*>(cp) = make_float4(o[0], o[1], o[2], o[3]);
                *reinterpret_cast<float4*>(cp + 4) = make_float4(o[4], o[5], o[6], o[7]);
            }
        }
    }
}

// ---------------- residual copy ----------------
__global__ void copy_kernel() {
    int idx4 = blockIdx.x * blockDim.x + threadIdx.x;
    if (idx4 < NN * 16)
        reinterpret_cast<float4*>(g_acc)[idx4] = reinterpret_cast<const float4*>(g_h)[idx4];
}

// ---------------- fused edge kernel: warp-specialized producer/consumer pipeline ----
// Producers (warps 0-3): stage At[tile t] -> mma -> EW[b] (+bias)
// Consumers (warps 4-7): message + run-compressed scatter for tile t-1 from EW[1-b]
// One __syncthreads per tile swaps buffers.
//
// smem (bytes):
//   [0,512)      bias[128]
//   [512,1024)   src[2][64]
//   [1024,1536)  dst[2][64]
//   [1536,26112) Bp prepacked B fragments (3072 uint2)
//   [26112,39936) At: 48 x 72 tf32 words
//   [39936,107520) EW: 2 x 64 x 132 floats
#define AT_LD  72
#define EW_LD  132
#define SM_BP  1536
#define SM_AT  26112
#define SM_EW  39936
#define FE_SMEM (SM_EW + 2 * EPT * EW_LD * 4)   // 107520

__global__ __launch_bounds__(256, 2) void fused_edge_kernel(
        const float* __restrict__ Wce, const float* __restrict__ bce) {
    extern __shared__ char base[];
    float*    bias_s = (float*)(base);
    int*      src_s  = (int*)(base + 512);     // [2][64]
    int*      dst_s  = (int*)(base + 1024);    // [2][64]
    uint2*    Bp     = (uint2*)(base + SM_BP);
    uint32_t* At     = (uint32_t*)(base + SM_AT);
    float*    EW_s   = (float*)(base + SM_EW); // [2][64*132]

    int tid = threadIdx.x;
    int lane = tid & 31, wid = tid >> 5;
    int gid = lane >> 2, tig = lane & 3;

    if (tid < 128) bias_s[tid] = bce[tid];
    // prepack B fragments
    for (int i = tid; i < 3072; i += 256) {
        int l = i & 31, nt = (i >> 5) & 15, kk = i >> 9;
        int g = l >> 2, t = l & 3;
        int k0 = 8 * kk + t, k1 = k0 + 4, n = 8 * nt + g;
        uint32_t b0 = (k0 < FE) ? to_tf32(Wce[k0 * 128 + n]) : 0u;
        uint32_t b1 = (k1 < FE) ? to_tf32(Wce[k1 * 128 + n]) : 0u;
        Bp[i] = make_uint2(b0, b1);
    }
    // zero At k-padding rows 41..47 once (never overwritten)
    for (int i = tid; i < 7 * AT_LD; i += 256) At[FE * AT_LD + i] = 0u;
    __syncthreads();

    const int ntiles = NE / EPT;   // 12500
    for (int k = 0;; k++) {
        int tp = blockIdx.x + k * gridDim.x;         // tile to produce
        int tc = blockIdx.x + (k - 1) * gridDim.x;   // tile to consume
        if (tc >= ntiles) break;
        int b = k & 1;

        if (wid < 4) {
            // ================= producer =================
            if (tp < ntiles) {
                int e0 = tp * EPT;
                for (int i = tid; i < EPT * FE; i += 128) {
                    int r = i / FE;
                    At[(i - r * FE) * AT_LD + r] = to_tf32(g_eap[(ll)e0 * FE + i]);
                }
                if (tid < EPT) src_s[b * EPT + tid] = g_srcp[e0 + tid];
                else           dst_s[b * EPT + tid - EPT] = g_dstp[e0 + tid - EPT];
                asm volatile("bar.sync 1, 128;" ::: "memory");

                int row0 = wid * 16;
                float c[16][4];
                #pragma unroll
                for (int nt = 0; nt < 16; nt++)
                    #pragma unroll
                    for (int q = 0; q < 4; q++) c[nt][q] = 0.f;
                #pragma unroll
                for (int kk = 0; kk < 6; kk++) {
                    uint32_t a0 = At[(8 * kk + tig) * AT_LD + row0 + gid];
                    uint32_t a1 = At[(8 * kk + tig) * AT_LD + row0 + gid + 8];
                    uint32_t a2 = At[(8 * kk + tig + 4) * AT_LD + row0 + gid];
                    uint32_t a3 = At[(8 * kk + tig + 4) * AT_LD + row0 + gid + 8];
                    #pragma unroll
                    for (int nt = 0; nt < 16; nt++) {
                        uint2 bb = Bp[(kk * 16 + nt) * 32 + lane];
                        mma_tf32(c[nt], a0, a1, a2, a3, bb.x, bb.y);
                    }
                }
                float* EWb = EW_s + b * EPT * EW_LD;
                #pragma unroll
                for (int nt = 0; nt < 16; nt++) {
                    float2 bi = *reinterpret_cast<const float2*>(&bias_s[nt * 8 + 2 * tig]);
                    *reinterpret_cast<float2*>(&EWb[(row0 + gid) * EW_LD + nt * 8 + 2 * tig]) =
                        make_float2(c[nt][0] + bi.x, c[nt][1] + bi.y);
                    *reinterpret_cast<float2*>(&EWb[(row0 + gid + 8) * EW_LD + nt * 8 + 2 * tig]) =
                        make_float2(c[nt][2] + bi.x, c[nt][3] + bi.y);
                }
            }
        } else {
            // ================= consumer =================
            if (tc >= 0) {
                int row0 = (wid - 4) * 16;
                const float* EWc = EW_s + (1 - b) * EPT * EW_LD;
                const int* srcc = src_s + (1 - b) * EPT;
                const int* dstc = dst_s + (1 - b) * EPT;
                float2 fj[16], sj[16];
                #pragma unroll
                for (int r = 0; r < 16; r++) {
                    int s = srcc[row0 + r];
                    fj[r] = *reinterpret_cast<const float2*>(&g_HN[(ll)s * 256 + 128 + 2 * lane]);
                    sj[r] = *reinterpret_cast<const float2*>(&g_HN[(ll)s * 256 + 192 + 2 * lane]);
                }
                int dprev = -1;
                float fi0 = 0.f, fi1 = 0.f, si0 = 0.f, si1 = 0.f, a0 = 0.f, a1 = 0.f;
                #pragma unroll
                for (int r = 0; r < 16; r++) {
                    int e = row0 + r;
                    int d = dstc[e];   // warp-uniform
                    if (d != dprev) {
                        if (dprev >= 0) red2(&g_acc[(ll)dprev * HD + 2 * lane], a0, a1);
                        float2 t0 = *reinterpret_cast<const float2*>(&g_HN[(ll)d * 256 + 2 * lane]);
                        float2 t1 = *reinterpret_cast<const float2*>(&g_HN[(ll)d * 256 + 64 + 2 * lane]);
                        fi0 = t0.x; fi1 = t0.y; si0 = t1.x; si1 = t1.y;
                        a0 = 0.f; a1 = 0.f;
                        dprev = d;
                    }
                    float2 ef = *reinterpret_cast<const float2*>(&EWc[e * EW_LD + 2 * lane]);
                    float2 es = *reinterpret_cast<const float2*>(&EWc[e * EW_LD + 64 + 2 * lane]);
                    a0 += sigmoid_f(ef.x + fi0 + fj[r].x) * softplus_f(es.x + si0 + sj[r].x);
                    a1 += sigmoid_f(ef.y + fi1 + fj[r].y) * softplus_f(es.y + si1 + sj[r].y);
                }
                if (dprev >= 0) red2(&g_acc[(ll)dprev * HD + 2 * lane], a0, a1);
            }
        }
        __syncthreads();
    }
}

// ---------------- BN stats ----------------
__global__ void stats_kernel(int a) {
    __shared__ float s_s[HD], s_q[HD];
    int tid = threadIdx.x;
    if (tid < HD) { s_s[tid] = 0.f; s_q[tid] = 0.f; }
    __syncthreads();
    int col4 = tid & 15;
    float4 ls = make_float4(0.f, 0.f, 0.f, 0.f), lq = ls;
    const float4* acc4 = reinterpret_cast<const float4*>(g_acc);
    for (int idx4 = blockIdx.x * blockDim.x + tid; idx4 < NN * 16; idx4 += gridDim.x * blockDim.x) {
        float4 v = acc4[idx4];
        ls.x += v.x; lq.x = fmaf(v.x, v.x, lq.x);
        ls.y += v.y; lq.y = fmaf(v.y, v.y, lq.y);
        ls.z += v.z; lq.z = fmaf(v.z, v.z, lq.z);
        ls.w += v.w; lq.w = fmaf(v.w, v.w, lq.w);
    }
    atomicAdd(&s_s[col4 * 4 + 0], ls.x); atomicAdd(&s_q[col4 * 4 + 0], lq.x);
    atomicAdd(&s_s[col4 * 4 + 1], ls.y); atomicAdd(&s_q[col4 * 4 + 1], lq.y);
    atomicAdd(&s_s[col4 * 4 + 2], ls.z); atomicAdd(&s_q[col4 * 4 + 2], lq.z);
    atomicAdd(&s_s[col4 * 4 + 3], ls.w); atomicAdd(&s_q[col4 * 4 + 3], lq.w);
    __syncthreads();
    if (tid < HD) {
        atomicAdd(&g_sum[a * HD + tid], s_s[tid]);
        atomicAdd(&g_sumsq[a * HD + tid], s_q[tid]);
    }
}

// ---------------- BN normalize (+relu) (+next residual) (+pooling) ----------------
__global__ void bn_kernel(const float* __restrict__ gamma, const float* __restrict__ beta,
                          int a, int do_relu, int write_acc, int do_pool,
                          const int* __restrict__ batch) {
    int idx4 = blockIdx.x * blockDim.x + threadIdx.x;
    if (idx4 >= NN * 16) return;
    int col4 = idx4 & 15;
    int node = idx4 >> 4;
    const float invn = 1.0f / (float)NN;
    float4 su = reinterpret_cast<const float4*>(g_sum)[a * 16 + col4];
    float4 sq = reinterpret_cast<const float4*>(g_sumsq)[a * 16 + col4];
    float4 ga = reinterpret_cast<const float4*>(gamma)[col4];
    float4 be = reinterpret_cast<const float4*>(beta)[col4];
    float4 v = reinterpret_cast<const float4*>(g_acc)[idx4];
    #pragma unroll
    for (int c = 0; c < 4; c++) {
        float mu = (&su.x)[c] * invn;
        float var = fmaxf((&sq.x)[c] * invn - mu * mu, 0.f);
        float y = ((&v.x)[c] - mu) * rsqrtf(var + BN_EPS) * (&ga.x)[c] + (&be.x)[c];
        if (do_relu) y = fmaxf(y, 0.f);
        (&v.x)[c] = y;
    }
    reinterpret_cast<float4*>(g_h)[idx4] = v;
    if (write_acc) reinterpret_cast<float4*>(g_acc)[idx4] = v;
    if (do_pool) {
        int b = batch[node];
        red4(&g_gsum[b * HD + col4 * 4], v);
        if (col4 == 0) atomicAdd(&g_gcnt[b], 1.0f);
    }
}

// ---------------- final MLP ----------------
__global__ void mlp_kernel(const float* __restrict__ W1, const float* __restrict__ b1,
                           const float* __restrict__ W2, const float* __restrict__ b2,
                           const float* __restrict__ Wo, const float* __restrict__ bo,
                           float* __restrict__ out) {
    __shared__ float sW1[HD * HD], sW2[HD * HD], sWo[HD], sb1[HD], sb2[HD];
    int tid = threadIdx.x;
    for (int i = tid; i < HD * HD; i += blockDim.x) { sW1[i] = W1[i]; sW2[i] = W2[i]; }
    if (tid < HD) { sWo[tid] = Wo[tid]; sb1[tid] = b1[tid]; sb2[tid] = b2[tid]; }
    __syncthreads();
    if (tid < NG) {
        float inv = 1.0f / fmaxf(g_gcnt[tid], 1.0f);
        float v[HD], y[HD];
        #pragma unroll
        for (int k = 0; k < HD; k++) v[k] = g_gsum[tid * HD + k] * inv;
        #pragma unroll 1
        for (int j = 0; j < HD; j++) {
            float s = sb1[j];
            #pragma unroll
            for (int k = 0; k < HD; k++) s = fmaf(v[k], sW1[k * HD + j], s);
            y[j] = fmaxf(s, 0.0f) + __logf(1.0f + __expf(-fabsf(s)));
        }
        float o = bo[0];
        #pragma unroll 1
        for (int j = 0; j < HD; j++) {
            float s = sb2[j];
            #pragma unroll
            for (int k = 0; k < HD; k++) s = fmaf(y[k], sW2[k * HD + j], s);
            o = fmaf(fmaxf(s, 0.0f) + __logf(1.0f + __expf(-fabsf(s))), sWo[j], o);
        }
        out[tid] = o;
    }
}

// ---------------- host launcher ----------------
template <int K, int NC, int CT, int RT, int RPT>
static void launch_gemm(const float* A, const float* B, const float* bias, float* C,
                        int M, int ldb, int ldc, int nsplit) {
    constexpr int TR = RT * RPT;
    constexpr int KP = K + 1;
    static_assert(CT * 8 == NC, "col threads x 8 must equal NC");
    size_t sm = (size_t)(K * NC + TR * KP) * sizeof(float);
    if (sm > 48 * 1024) {
        cudaFuncSetAttribute(gemm_bias_kernel<K, NC, CT, RT, RPT>,
                             cudaFuncAttributeMaxDynamicSharedMemorySize, (int)sm);
    }
    dim3 grid((M + TR - 1) / TR, nsplit);
    gemm_bias_kernel<K, NC, CT, RT, RPT><<<grid, CT * RT, sm>>>(A, B, bias, C, M, ldb, ldc);
}

extern "C" void kernel_launch(void* const* d_in, const int* in_sizes, int n_in,
                              void* d_out, int out_size) {
    const float* x         = (const float*)d_in[0];
    const float* edge_attr = (const float*)d_in[1];
    const int*   ei        = (const int*)d_in[2];
    const int*   batch     = (const int*)d_in[3];
    const float* W_emb1    = (const float*)d_in[4];
    const float* b_emb1    = (const float*)d_in[5];
    const float* W_emb2    = (const float*)d_in[6];
    const float* b_emb2    = (const float*)d_in[7];
    const float* Wf        = (const float*)d_in[8];
    const float* bf        = (const float*)d_in[9];
    const float* Ws        = (const float*)d_in[10];
    const float* bs        = (const float*)d_in[11];
    const float* gamma     = (const float*)d_in[12];
    const float* beta      = (const float*)d_in[13];
    const float* W1        = (const float*)d_in[14];
    const float* b1        = (const float*)d_in[15];
    const float* W2        = (const float*)d_in[16];
    const float* b2        = (const float*)d_in[17];
    const float* Wo        = (const float*)d_in[18];
    const float* bo        = (const float*)d_in[19];
    float* out = (float*)d_out;

    float *p_h, *p_Wce, *p_bce, *p_Wnode, *p_HN;
    cudaGetSymbolAddress((void**)&p_h, g_h);
    cudaGetSymbolAddress((void**)&p_Wce, g_Wce);
    cudaGetSymbolAddress((void**)&p_bce, g_bce);
    cudaGetSymbolAddress((void**)&p_Wnode, g_Wnode);
    cudaGetSymbolAddress((void**)&p_HN, g_HN);

    // fold weights + zero counters/stats
    prep_kernel<<<255, 256>>>(W_emb2, b_emb2, Wf, bf, Ws, bs);
    zero_kernel<<<NBLK, 256>>>();

    // sort edges by dst (counting sort) + permute edge_attr
    hist_kernel<<<(NE + 255) / 256, 256>>>(ei);
    scan1_kernel<<<NBLK, 256>>>();
    scan2_kernel<<<1, 256>>>();
    scan3_kernel<<<NBLK, 256>>>();
    scatter_kernel<<<(NE + 255) / 256, 256>>>(ei);
    permute_ea_kernel<<<1600, 256>>>(edge_attr);

    // h0 = x @ W_emb1 + b_emb1
    launch_gemm<FX, HD, 8, 32, 4>(x, W_emb1, b_emb1, p_h, NN, HD, HD, 1);
    copy_kernel<<<(NN * 16 + 255) / 256, 256>>>();

    cudaFuncSetAttribute(fused_edge_kernel,
                         cudaFuncAttributeMaxDynamicSharedMemorySize, FE_SMEM);

    for (int a = 0; a < NCV; a++) {
        // HN = h @ Wnode[a], 4 column chunks of 64
        launch_gemm<HD, HD, 8, 32, 4>(p_h, p_Wnode + (ll)a * HD * 4 * HD,
                                      nullptr, p_HN, NN, 4 * HD, 4 * HD, 4);
        fused_edge_kernel<<<296, 256, FE_SMEM>>>(p_Wce + a * FE * 2 * HD,
                                                 p_bce + a * 2 * HD);
        stats_kernel<<<296, 256>>>(a);
        bn_kernel<<<(NN * 16 + 255) / 256, 256>>>(gamma + a * HD, beta + a * HD, a,
                                                  a < NCV - 1 ? 1 : 0,
                                                  a < NCV - 1 ? 1 : 0,
                                                  a == NCV - 1 ? 1 : 0, batch);
    }

    mlp_kernel<<<1, 128>>>(W1, b1, W2, b2, Wo, bo, out);
}

// round 10
// speedup vs baseline: 1.0871x; 1.0871x over previous
#include <cuda_runtime.h>
#include <math.h>
#include <stdint.h>

#define NN 50000      // nodes
#define NE 800000     // edges
#define NG 128        // graphs
#define FX 92         // node feature dim
#define FE 41         // edge feature dim
#define HD 64         // hidden
#define NCV 3         // conv layers
#define BN_EPS 1e-5f
#define NBLK 196      // scan blocks: 196*256 = 50176 >= NN
#define EPT 128       // edges per tile

typedef unsigned long long ull;
typedef long long ll;

// ---------------- device scratch ----------------
__device__ float g_h[NN * HD];
__device__ float g_acc[NN * HD];
__device__ float g_HN[NN * 4 * HD];                   // [N,256]: [f_i|s_i|f_j|s_j]
__device__ float g_Wce[NCV * FE * 2 * HD];
__device__ float g_bce[NCV * 2 * HD];
__device__ float g_Wnode[NCV * HD * 4 * HD];
__device__ float g_sum[NCV * HD];
__device__ float g_sumsq[NCV * HD];
__device__ float g_gsum[NG * HD];
__device__ float g_gcnt[NG];
// sort-by-dst machinery
__device__ int   g_deg[NN];
__device__ int   g_cursor[NN];
__device__ int   g_rp[NN];
__device__ int   g_bsum[256];
__device__ int   g_perm[NE];
__device__ int   g_srcp[NE];
__device__ int   g_dstp[NE];

// ---------------- helpers ----------------
__device__ __forceinline__ ull pack2(float a, float b) {
    ull r; asm("mov.b64 %0, {%1, %2};" : "=l"(r) : "f"(a), "f"(b)); return r;
}
__device__ __forceinline__ void unpack2(ull v, float& a, float& b) {
    asm("mov.b64 {%0, %1}, %2;" : "=f"(a), "=f"(b) : "l"(v));
}
__device__ __forceinline__ void fma2(ull& d, ull a, ull b) {
    asm("fma.rn.f32x2 %0, %1, %2, %0;" : "+l"(d) : "l"(a), "l"(b));
}
// sigmoid(x) = 0.5*tanh(0.5x)+0.5  (1 MUFU)
__device__ __forceinline__ float sigmoid_f(float x) {
    float t;
    asm("tanh.approx.f32 %0, %1;" : "=f"(t) : "f"(x * 0.5f));
    return fmaf(t, 0.5f, 0.5f);
}
__device__ __forceinline__ float softplus_f(float x) {
    return fmaxf(x, 0.0f) + __logf(1.0f + __expf(-fabsf(x)));
}
__device__ __forceinline__ void red4(float* p, float4 v) {
    asm volatile("red.global.add.v4.f32 [%0], {%1,%2,%3,%4};"
                 :: "l"(p), "f"(v.x), "f"(v.y), "f"(v.z), "f"(v.w) : "memory");
}
__device__ __forceinline__ void red2(float* p, float a, float b) {
    asm volatile("red.global.add.v2.f32 [%0], {%1,%2};"
                 :: "l"(p), "f"(a), "f"(b) : "memory");
}
__device__ __forceinline__ uint32_t to_tf32(float f) {
    uint32_t r; asm("cvt.rna.tf32.f32 %0, %1;" : "=r"(r) : "f"(f)); return r;
}
__device__ __forceinline__ void mma_tf32(float c[4], uint32_t a0, uint32_t a1,
                                         uint32_t a2, uint32_t a3,
                                         uint32_t b0, uint32_t b1) {
    asm volatile(
        "mma.sync.aligned.m16n8k8.row.col.f32.tf32.tf32.f32 "
        "{%0,%1,%2,%3}, {%4,%5,%6,%7}, {%8,%9}, {%0,%1,%2,%3};"
        : "+f"(c[0]), "+f"(c[1]), "+f"(c[2]), "+f"(c[3])
        : "r"(a0), "r"(a1), "r"(a2), "r"(a3), "r"(b0), "r"(b1));
}

// ---------------- prep: fold weights ----------------
__global__ void prep_kernel(const float* __restrict__ W_emb2, const float* __restrict__ b_emb2,
                            const float* __restrict__ Wf, const float* __restrict__ bf,
                            const float* __restrict__ Ws, const float* __restrict__ bs) {
    int idx = blockIdx.x * blockDim.x + threadIdx.x;
    const int N_WCE = NCV * FE * 2 * HD;
    const int N_BCE = NCV * 2 * HD;
    const int N_WND = NCV * HD * 4 * HD;
    if (idx < N_WCE) {
        int j = idx % (2 * HD);
        int k = (idx / (2 * HD)) % FE;
        int a = idx / (2 * HD * FE);
        const float* Wb = (j < HD) ? Wf : Ws;
        int jj = j & (HD - 1);
        float s = 0.f;
        #pragma unroll 8
        for (int m = 0; m < HD; m++)
            s = fmaf(W_emb2[k * HD + m], Wb[(a * 3 * HD + 2 * HD + m) * HD + jj], s);
        g_Wce[idx] = s;
    } else if (idx < N_WCE + N_BCE) {
        int t = idx - N_WCE;
        int j = t % (2 * HD);
        int a = t / (2 * HD);
        const float* Wb = (j < HD) ? Wf : Ws;
        const float* bb = (j < HD) ? bf : bs;
        int jj = j & (HD - 1);
        float s = bb[a * HD + jj];
        #pragma unroll 8
        for (int m = 0; m < HD; m++)
            s = fmaf(b_emb2[m], Wb[(a * 3 * HD + 2 * HD + m) * HD + jj], s);
        g_bce[t] = s;
    } else if (idx < N_WCE + N_BCE + N_WND) {
        int t = idx - N_WCE - N_BCE;
        int j = t % (4 * HD);
        int m = (t / (4 * HD)) % HD;
        int a = t / (4 * HD * HD);
        int blk = j / HD;                 // 0:f_i 1:s_i 2:f_j 3:s_j
        int jj = j & (HD - 1);
        const float* Wsel = (blk & 1) ? Ws : Wf;
        int roff = (blk >= 2) ? HD : 0;
        g_Wnode[t] = Wsel[(a * 3 * HD + roff + m) * HD + jj];
    }
}

// ---------------- zero counters/stats ----------------
__global__ void zero_kernel() {
    int i = blockIdx.x * blockDim.x + threadIdx.x;
    if (i < NN) { g_deg[i] = 0; g_cursor[i] = 0; }
    if (i < NCV * HD) { g_sum[i] = 0.f; g_sumsq[i] = 0.f; }
    if (i < NG * HD) g_gsum[i] = 0.f;
    if (i < NG) g_gcnt[i] = 0.f;
}

// ---------------- sort by dst ----------------
__global__ void hist_kernel(const int* __restrict__ ei) {
    int e = blockIdx.x * blockDim.x + threadIdx.x;
    if (e < NE) atomicAdd(&g_deg[ei[NE + e]], 1);
}
__global__ void scan1_kernel() {
    __shared__ int s[256];
    int tid = threadIdx.x;
    int i = blockIdx.x * 256 + tid;
    int v = (i < NN) ? g_deg[i] : 0;
    s[tid] = v; __syncthreads();
    #pragma unroll
    for (int off = 1; off < 256; off <<= 1) {
        int t = (tid >= off) ? s[tid - off] : 0;
        __syncthreads();
        s[tid] += t;
        __syncthreads();
    }
    if (i < NN) g_rp[i] = s[tid] - v;
    if (tid == 255) g_bsum[blockIdx.x] = s[255];
}
__global__ void scan2_kernel() {
    __shared__ int s[256];
    int tid = threadIdx.x;
    int v = (tid < NBLK) ? g_bsum[tid] : 0;
    s[tid] = v; __syncthreads();
    #pragma unroll
    for (int off = 1; off < 256; off <<= 1) {
        int t = (tid >= off) ? s[tid - off] : 0;
        __syncthreads();
        s[tid] += t;
        __syncthreads();
    }
    if (tid < NBLK) g_bsum[tid] = s[tid] - v;
}
__global__ void scan3_kernel() {
    int i = blockIdx.x * 256 + threadIdx.x;
    if (i < NN) g_rp[i] += g_bsum[blockIdx.x];
}
__global__ void scatter_kernel(const int* __restrict__ ei) {
    int e = blockIdx.x * blockDim.x + threadIdx.x;
    if (e >= NE) return;
    int d = ei[NE + e];
    int s = ei[e];
    int pos = g_rp[d] + atomicAdd(&g_cursor[d], 1);
    g_perm[pos] = e;
    g_srcp[pos] = s;
    g_dstp[pos] = d;
}

// ---------------- generic fp32 GEMM with f32x2 inner loop + optional fused BN on A ----
// If bnsum != nullptr: A is a RAW accumulator; per-column BN (stats slot given by
// bnsum/bnsq, gamma/beta) + optional relu applied while staging; normalized rows
// written back to wb (from blockIdx.y==0 only; wb is a DIFFERENT buffer than A).
template <int K, int NC, int CT, int RT, int RPT>
__global__ void gemm_bias_kernel(const float* __restrict__ A, const float* __restrict__ B,
                                 const float* __restrict__ bias, float* __restrict__ C,
                                 float* __restrict__ C2, int M, int ldb, int ldc,
                                 const float* __restrict__ bnsum, const float* __restrict__ bnsq,
                                 const float* __restrict__ bngam, const float* __restrict__ bnbet,
                                 int bnrelu, float* __restrict__ wb) {
    constexpr int TR = RT * RPT;
    constexpr int KP = K + 1;
    constexpr int NT = CT * RT;
    extern __shared__ float smem[];
    float* Bs = smem;
    float* As = smem + K * NC;
    float* scl = As + TR * KP;
    float* sft = scl + K;
    int tid = threadIdx.x;
    int tx = tid % CT;
    int ty = tid / CT;
    int c0 = blockIdx.y * NC;
    for (int i = tid; i < K * NC; i += NT) {
        int k = i / NC, c = i - k * NC;
        Bs[i] = B[k * ldb + c0 + c];
    }
    if (bnsum && tid < K) {
        const float invn = 1.0f / (float)M;
        float mu = bnsum[tid] * invn;
        float var = fmaxf(bnsq[tid] * invn - mu * mu, 0.f);
        float sc = rsqrtf(var + BN_EPS) * bngam[tid];
        scl[tid] = sc;
        sft[tid] = bnbet[tid] - mu * sc;
    }
    ull bp[4];
    #pragma unroll
    for (int c = 0; c < 4; c++) {
        float b0 = bias ? bias[c0 + tx * 8 + 2 * c] : 0.f;
        float b1 = bias ? bias[c0 + tx * 8 + 2 * c + 1] : 0.f;
        bp[c] = pack2(b0, b1);
    }
    for (int tile = blockIdx.x; (ll)tile * TR < M; tile += gridDim.x) {
        int row0 = tile * TR;
        __syncthreads();
        for (int i = tid; i < TR * K; i += NT) {
            int r = i / K;
            int k = i - r * K;
            int gr = row0 + r;
            float v = (gr < M) ? A[(ll)gr * K + k] : 0.f;
            if (bnsum) {
                v = fmaf(v, scl[k], sft[k]);
                if (bnrelu) v = fmaxf(v, 0.f);
                if (wb && blockIdx.y == 0 && gr < M) wb[(ll)gr * K + k] = v;
            }
            As[r * KP + k] = v;
        }
        __syncthreads();
        ull acc[RPT][4];
        #pragma unroll
        for (int r = 0; r < RPT; r++)
            #pragma unroll
            for (int c = 0; c < 4; c++) acc[r][c] = bp[c];
        for (int k = 0; k < K; k++) {
            float4 b0 = *reinterpret_cast<const float4*>(&Bs[k * NC + tx * 8]);
            float4 b1 = *reinterpret_cast<const float4*>(&Bs[k * NC + tx * 8 + 4]);
            ull p0 = pack2(b0.x, b0.y), p1 = pack2(b0.z, b0.w);
            ull p2 = pack2(b1.x, b1.y), p3 = pack2(b1.z, b1.w);
            #pragma unroll
            for (int r = 0; r < RPT; r++) {
                float a = As[(ty * RPT + r) * KP + k];
                ull ad = pack2(a, a);
                fma2(acc[r][0], ad, p0);
                fma2(acc[r][1], ad, p1);
                fma2(acc[r][2], ad, p2);
                fma2(acc[r][3], ad, p3);
            }
        }
        #pragma unroll
        for (int r = 0; r < RPT; r++) {
            int gr = row0 + ty * RPT + r;
            if (gr < M) {
                float o[8];
                #pragma unroll
                for (int c = 0; c < 4; c++) unpack2(acc[r][c], o[2 * c], o[2 * c + 1]);
                float* cp = &C[(ll)gr * ldc + c0 + tx * 8];
                *reinterpret_cast<float4*>(cp) = make_float4(o[0], o[1], o[2], o[3]);
                *reinterpret_cast<float4*>(cp + 4) = make_float4(o[4], o[5], o[6], o[7]);
                if (C2) {
                    float* cp2 = &C2[(ll)gr * ldc + c0 + tx * 8];
                    *reinterpret_cast<float4*>(cp2) = make_float4(o[0], o[1], o[2], o[3]);
                    *reinterpret_cast<float4*>(cp2 + 4) = make_float4(o[4], o[5], o[6], o[7]);
                }
            }
        }
    }
}

// ---------------- fused: mma.sync tf32 edge GEMM + message + CSR scatter ----------------
// (R8 structure; staging reads edge_attr via g_perm directly — no permuted copy)
#define AT_LD  136
#define EW_LD  132
#define SM_BP  1536
#define SM_AT  (SM_BP + 3072 * 8)          // 26112
#define SM_EW  SM_AT                        // overlapped with At
#define FE_SMEM (SM_AT + EPT * EW_LD * 4)  // 93696

__global__ __launch_bounds__(256, 2) void fused_edge_kernel(
        const float* __restrict__ ea, float* __restrict__ acc,
        const float* __restrict__ Wce, const float* __restrict__ bce) {
    extern __shared__ char base[];
    float*    bias_s = (float*)(base);
    int*      src_s  = (int*)(base + 512);
    int*      dst_s  = (int*)(base + 1024);
    uint2*    Bp     = (uint2*)(base + SM_BP);
    uint32_t* At     = (uint32_t*)(base + SM_AT);
    float*    EW_s   = (float*)(base + SM_EW);

    int tid = threadIdx.x;
    int lane = tid & 31, wid = tid >> 5;
    int gid = lane >> 2, tig = lane & 3;

    if (tid < 128) bias_s[tid] = bce[tid];
    // prepack B fragments
    for (int i = tid; i < 3072; i += 256) {
        int l = i & 31, nt = (i >> 5) & 15, kk = i >> 9;
        int g = l >> 2, t = l & 3;
        int k0 = 8 * kk + t, k1 = k0 + 4, n = 8 * nt + g;
        uint32_t b0 = (k0 < FE) ? to_tf32(Wce[k0 * 128 + n]) : 0u;
        uint32_t b1 = (k1 < FE) ? to_tf32(Wce[k1 * 128 + n]) : 0u;
        Bp[i] = make_uint2(b0, b1);
    }

    const int ntiles = NE / EPT;   // 6250
    int row0 = wid * 16;
    for (int tile = blockIdx.x; tile < ntiles; tile += gridDim.x) {
        int e0 = tile * EPT;
        __syncthreads();   // prev msg phase done before At (=EW region) overwrite
        // stage A transposed + tf32-converted (gather rows via perm)
        for (int i = tid; i < EPT * FE; i += 256) {
            int r = i / FE, k = i - r * FE;
            int e = g_perm[e0 + r];
            At[k * AT_LD + r] = to_tf32(ea[(ll)e * FE + k]);
        }
        for (int i = tid; i < 7 * AT_LD; i += 256) At[FE * AT_LD + i] = 0u;
        if (tid < EPT) {
            src_s[tid] = g_srcp[e0 + tid];
            dst_s[tid] = g_dstp[e0 + tid];
        }
        __syncthreads();

        // ---- mma phase: warp computes rows [row0,row0+16) x 128 cols ----
        {
            float c[16][4];
            #pragma unroll
            for (int nt = 0; nt < 16; nt++)
                #pragma unroll
                for (int q = 0; q < 4; q++) c[nt][q] = 0.f;
            #pragma unroll
            for (int kk = 0; kk < 6; kk++) {
                uint32_t a0 = At[(8 * kk + tig) * AT_LD + row0 + gid];
                uint32_t a1 = At[(8 * kk + tig) * AT_LD + row0 + gid + 8];
                uint32_t a2 = At[(8 * kk + tig + 4) * AT_LD + row0 + gid];
                uint32_t a3 = At[(8 * kk + tig + 4) * AT_LD + row0 + gid + 8];
                #pragma unroll
                for (int nt = 0; nt < 16; nt++) {
                    uint2 b = Bp[(kk * 16 + nt) * 32 + lane];
                    mma_tf32(c[nt], a0, a1, a2, a3, b.x, b.y);
                }
            }
            __syncthreads();   // all At reads complete before EW overwrites region
            #pragma unroll
            for (int nt = 0; nt < 16; nt++) {
                float2 bi = *reinterpret_cast<const float2*>(&bias_s[nt * 8 + 2 * tig]);
                *reinterpret_cast<float2*>(&EW_s[(row0 + gid) * EW_LD + nt * 8 + 2 * tig]) =
                    make_float2(c[nt][0] + bi.x, c[nt][1] + bi.y);
                *reinterpret_cast<float2*>(&EW_s[(row0 + gid + 8) * EW_LD + nt * 8 + 2 * tig]) =
                    make_float2(c[nt][2] + bi.x, c[nt][3] + bi.y);
            }
        }
        __syncthreads();

        // ---- message phase: warp handles edges [row0,row0+16), run-compressed ----
        {
            float2 fj[16], sj[16];
            #pragma unroll
            for (int r = 0; r < 16; r++) {
                int s = src_s[row0 + r];
                fj[r] = *reinterpret_cast<const float2*>(&g_HN[(ll)s * 256 + 128 + 2 * lane]);
                sj[r] = *reinterpret_cast<const float2*>(&g_HN[(ll)s * 256 + 192 + 2 * lane]);
            }
            int dprev = -1;
            float fi0 = 0.f, fi1 = 0.f, si0 = 0.f, si1 = 0.f, a0 = 0.f, a1 = 0.f;
            #pragma unroll
            for (int r = 0; r < 16; r++) {
                int e = row0 + r;
                int d = dst_s[e];   // warp-uniform
                if (d != dprev) {
                    if (dprev >= 0) red2(&acc[(ll)dprev * HD + 2 * lane], a0, a1);
                    float2 t0 = *reinterpret_cast<const float2*>(&g_HN[(ll)d * 256 + 2 * lane]);
                    float2 t1 = *reinterpret_cast<const float2*>(&g_HN[(ll)d * 256 + 64 + 2 * lane]);
                    fi0 = t0.x; fi1 = t0.y; si0 = t1.x; si1 = t1.y;
                    a0 = 0.f; a1 = 0.f;
                    dprev = d;
                }
                float2 ef = *reinterpret_cast<const float2*>(&EW_s[e * EW_LD + 2 * lane]);
                float2 es = *reinterpret_cast<const float2*>(&EW_s[e * EW_LD + 64 + 2 * lane]);
                a0 += sigmoid_f(ef.x + fi0 + fj[r].x) * softplus_f(es.x + si0 + sj[r].x);
                a1 += sigmoid_f(ef.y + fi1 + fj[r].y) * softplus_f(es.y + si1 + sj[r].y);
            }
            if (dprev >= 0) red2(&acc[(ll)dprev * HD + 2 * lane], a0, a1);
        }
    }
}

// ---------------- BN stats (from buf into slot a) ----------------
__global__ void stats_kernel(int a, const float* __restrict__ buf) {
    __shared__ float s_s[HD], s_q[HD];
    int tid = threadIdx.x;
    if (tid < HD) { s_s[tid] = 0.f; s_q[tid] = 0.f; }
    __syncthreads();
    int col4 = tid & 15;
    float4 ls = make_float4(0.f, 0.f, 0.f, 0.f), lq = ls;
    const float4* acc4 = reinterpret_cast<const float4*>(buf);
    for (int idx4 = blockIdx.x * blockDim.x + tid; idx4 < NN * 16; idx4 += gridDim.x * blockDim.x) {
        float4 v = acc4[idx4];
        ls.x += v.x; lq.x = fmaf(v.x, v.x, lq.x);
        ls.y += v.y; lq.y = fmaf(v.y, v.y, lq.y);
        ls.z += v.z; lq.z = fmaf(v.z, v.z, lq.z);
        ls.w += v.w; lq.w = fmaf(v.w, v.w, lq.w);
    }
    atomicAdd(&s_s[col4 * 4 + 0], ls.x); atomicAdd(&s_q[col4 * 4 + 0], lq.x);
    atomicAdd(&s_s[col4 * 4 + 1], ls.y); atomicAdd(&s_q[col4 * 4 + 1], lq.y);
    atomicAdd(&s_s[col4 * 4 + 2], ls.z); atomicAdd(&s_q[col4 * 4 + 2], lq.z);
    atomicAdd(&s_s[col4 * 4 + 3], ls.w); atomicAdd(&s_q[col4 * 4 + 3], lq.w);
    __syncthreads();
    if (tid < HD) {
        atomicAdd(&g_sum[a * HD + tid], s_s[tid]);
        atomicAdd(&g_sumsq[a * HD + tid], s_q[tid]);
    }
}

// ---------------- final BN + pooling (last layer only) ----------------
__global__ void bn_kernel(const float* __restrict__ gamma, const float* __restrict__ beta,
                          int a, const float* __restrict__ buf,
                          const int* __restrict__ batch) {
    int idx4 = blockIdx.x * blockDim.x + threadIdx.x;
    if (idx4 >= NN * 16) return;
    int col4 = idx4 & 15;
    int node = idx4 >> 4;
    const float invn = 1.0f / (float)NN;
    float4 su = reinterpret_cast<const float4*>(g_sum)[a * 16 + col4];
    float4 sq = reinterpret_cast<const float4*>(g_sumsq)[a * 16 + col4];
    float4 ga = reinterpret_cast<const float4*>(gamma)[col4];
    float4 be = reinterpret_cast<const float4*>(beta)[col4];
    float4 v = reinterpret_cast<const float4*>(buf)[idx4];
    #pragma unroll
    for (int c = 0; c < 4; c++) {
        float mu = (&su.x)[c] * invn;
        float var = fmaxf((&sq.x)[c] * invn - mu * mu, 0.f);
        (&v.x)[c] = ((&v.x)[c] - mu) * rsqrtf(var + BN_EPS) * (&ga.x)[c] + (&be.x)[c];
    }
    int b = batch[node];
    red4(&g_gsum[b * HD + col4 * 4], v);
    if (col4 == 0) atomicAdd(&g_gcnt[b], 1.0f);
}

// ---------------- final MLP ----------------
__global__ void mlp_kernel(const float* __restrict__ W1, const float* __restrict__ b1,
                           const float* __restrict__ W2, const float* __restrict__ b2,
                           const float* __restrict__ Wo, const float* __restrict__ bo,
                           float* __restrict__ out) {
    __shared__ float sW1[HD * HD], sW2[HD * HD], sWo[HD], sb1[HD], sb2[HD];
    int tid = threadIdx.x;
    for (int i = tid; i < HD * HD; i += blockDim.x) { sW1[i] = W1[i]; sW2[i] = W2[i]; }
    if (tid < HD) { sWo[tid] = Wo[tid]; sb1[tid] = b1[tid]; sb2[tid] = b2[tid]; }
    __syncthreads();
    if (tid < NG) {
        float inv = 1.0f / fmaxf(g_gcnt[tid], 1.0f);
        float v[HD], y[HD];
        #pragma unroll
        for (int k = 0; k < HD; k++) v[k] = g_gsum[tid * HD + k] * inv;
        #pragma unroll 1
        for (int j = 0; j < HD; j++) {
            float s = sb1[j];
            #pragma unroll
            for (int k = 0; k < HD; k++) s = fmaf(v[k], sW1[k * HD + j], s);
            y[j] = fmaxf(s, 0.0f) + __logf(1.0f + __expf(-fabsf(s)));
        }
        float o = bo[0];
        #pragma unroll 1
        for (int j = 0; j < HD; j++) {
            float s = sb2[j];
            #pragma unroll
            for (int k = 0; k < HD; k++) s = fmaf(y[k], sW2[k * HD + j], s);
            o = fmaf(fmaxf(s, 0.0f) + __logf(1.0f + __expf(-fabsf(s))), sWo[j], o);
        }
        out[tid] = o;
    }
}

// ---------------- host launcher ----------------
template <int K, int NC, int CT, int RT, int RPT>
static void launch_gemm(const float* A, const float* B, const float* bias, float* C,
                        float* C2, int M, int ldb, int ldc, int nsplit,
                        const float* bnsum, const float* bnsq,
                        const float* bngam, const float* bnbet, int bnrelu, float* wb) {
    constexpr int TR = RT * RPT;
    constexpr int KP = K + 1;
    static_assert(CT * 8 == NC, "col threads x 8 must equal NC");
    size_t sm = (size_t)(K * NC + TR * KP + 2 * K) * sizeof(float);
    if (sm > 48 * 1024) {
        cudaFuncSetAttribute(gemm_bias_kernel<K, NC, CT, RT, RPT>,
                             cudaFuncAttributeMaxDynamicSharedMemorySize, (int)sm);
    }
    dim3 grid((M + TR - 1) / TR, nsplit);
    gemm_bias_kernel<K, NC, CT, RT, RPT><<<grid, CT * RT, sm>>>(
        A, B, bias, C, C2, M, ldb, ldc, bnsum, bnsq, bngam, bnbet, bnrelu, wb);
}

extern "C" void kernel_launch(void* const* d_in, const int* in_sizes, int n_in,
                              void* d_out, int out_size) {
    const float* x         = (const float*)d_in[0];
    const float* edge_attr = (const float*)d_in[1];
    const int*   ei        = (const int*)d_in[2];
    const int*   batch     = (const int*)d_in[3];
    const float* W_emb1    = (const float*)d_in[4];
    const float* b_emb1    = (const float*)d_in[5];
    const float* W_emb2    = (const float*)d_in[6];
    const float* b_emb2    = (const float*)d_in[7];
    const float* Wf        = (const float*)d_in[8];
    const float* bf        = (const float*)d_in[9];
    const float* Ws        = (const float*)d_in[10];
    const float* bs        = (const float*)d_in[11];
    const float* gamma     = (const float*)d_in[12];
    const float* beta      = (const float*)d_in[13];
    const float* W1        = (const float*)d_in[14];
    const float* b1        = (const float*)d_in[15];
    const float* W2        = (const float*)d_in[16];
    const float* b2        = (const float*)d_in[17];
    const float* Wo        = (const float*)d_in[18];
    const float* bo        = (const float*)d_in[19];
    float* out = (float*)d_out;

    float *p_h, *p_acc, *p_Wce, *p_bce, *p_Wnode, *p_HN, *p_sum, *p_sumsq;
    cudaGetSymbolAddress((void**)&p_h, g_h);
    cudaGetSymbolAddress((void**)&p_acc, g_acc);
    cudaGetSymbolAddress((void**)&p_Wce, g_Wce);
    cudaGetSymbolAddress((void**)&p_bce, g_bce);
    cudaGetSymbolAddress((void**)&p_Wnode, g_Wnode);
    cudaGetSymbolAddress((void**)&p_HN, g_HN);
    cudaGetSymbolAddress((void**)&p_sum, g_sum);
    cudaGetSymbolAddress((void**)&p_sumsq, g_sumsq);

    // fold weights + zero counters/stats
    prep_kernel<<<255, 256>>>(W_emb2, b_emb2, Wf, bf, Ws, bs);
    zero_kernel<<<NBLK, 256>>>();

    // sort edges by dst (counting sort); no edge_attr permute — gathered at stage time
    hist_kernel<<<(NE + 255) / 256, 256>>>(ei);
    scan1_kernel<<<NBLK, 256>>>();
    scan2_kernel<<<1, 256>>>();
    scan3_kernel<<<NBLK, 256>>>();
    scatter_kernel<<<(NE + 255) / 256, 256>>>(ei);

    // h0 = x @ W_emb1 + b_emb1, dual-stored to g_h and g_acc
    launch_gemm<FX, HD, 8, 32, 4>(x, W_emb1, b_emb1, p_h, p_acc, NN, HD, HD, 1,
                                  nullptr, nullptr, nullptr, nullptr, 0, nullptr);

    cudaFuncSetAttribute(fused_edge_kernel,
                         cudaFuncAttributeMaxDynamicSharedMemorySize, FE_SMEM);

    // ping-pong: raw accumulator buffer per layer: L0->g_acc, L1->g_h, L2->g_acc
    float* rawbuf[3] = { p_acc, p_h, p_acc };   // edge-accumulate target
    float* srcbuf[3] = { p_h, p_acc, p_h };     // gemm A source

    for (int a = 0; a < NCV; a++) {
        const float* bnsum = (a == 0) ? nullptr : p_sum + (a - 1) * HD;
        const float* bnsq  = (a == 0) ? nullptr : p_sumsq + (a - 1) * HD;
        const float* bngam = (a == 0) ? nullptr : gamma + (a - 1) * HD;
        const float* bnbet = (a == 0) ? nullptr : beta + (a - 1) * HD;
        float* wb = (a == 0) ? nullptr : rawbuf[a];   // normalized h written here
        // HN = BN?(src) @ Wnode[a], 4 column chunks of 64
        launch_gemm<HD, HD, 8, 32, 4>(srcbuf[a], p_Wnode + (ll)a * HD * 4 * HD,
                                      nullptr, p_HN, nullptr, NN, 4 * HD, 4 * HD, 4,
                                      bnsum, bnsq, bngam, bnbet, 1, wb);
        fused_edge_kernel<<<296, 256, FE_SMEM>>>(edge_attr, rawbuf[a],
                                                 p_Wce + a * FE * 2 * HD,
                                                 p_bce + a * 2 * HD);
        stats_kernel<<<296, 256>>>(a, rawbuf[a]);
    }

    // final BN (no relu) + pooling from rawbuf[2] = g_acc
    bn_kernel<<<(NN * 16 + 255) / 256, 256>>>(gamma + 2 * HD, beta + 2 * HD, 2,
                                              rawbuf[2], batch);

    mlp_kernel<<<1, 128>>>(W1, b1, W2, b2, Wo, bo, out);
}

// round 11
// speedup vs baseline: 1.2066x; 1.1099x over previous
#include <cuda_runtime.h>
#include <math.h>
#include <stdint.h>

#define NN 50000      // nodes
#define NE 800000     // edges
#define NG 128        // graphs
#define FX 92         // node feature dim
#define FE 41         // edge feature dim
#define HD 64         // hidden
#define NCV 3         // conv layers
#define BN_EPS 1e-5f
#define NBLK 196      // scan blocks
#define EPW 16        // edges per warp-strip

typedef unsigned long long ull;
typedef long long ll;

// ---------------- device scratch ----------------
__device__ float g_h[NN * HD];
__device__ float g_acc[NN * HD];
__device__ float g_HN[NN * 4 * HD];                   // [N,256]: [f_i|s_i|f_j|s_j]
__device__ float g_Wce[NCV * FE * 2 * HD];
__device__ float g_bce[NCV * 2 * HD];
__device__ float g_Wnode[NCV * HD * 4 * HD];
__device__ float g_sum[NCV * HD];
__device__ float g_sumsq[NCV * HD];
__device__ float g_gsum[NG * HD];
__device__ float g_gcnt[NG];
// sort-by-dst machinery
__device__ int   g_deg[NN];
__device__ int   g_cursor[NN];
__device__ int   g_rp[NN];
__device__ int   g_bsum[256];
__device__ int   g_perm[NE];
__device__ int   g_srcp[NE];
__device__ int   g_dstp[NE];
__device__ float g_eap[(ll)NE * FE];   // permuted edge_attr

// ---------------- helpers ----------------
__device__ __forceinline__ ull pack2(float a, float b) {
    ull r; asm("mov.b64 %0, {%1, %2};" : "=l"(r) : "f"(a), "f"(b)); return r;
}
__device__ __forceinline__ void unpack2(ull v, float& a, float& b) {
    asm("mov.b64 {%0, %1}, %2;" : "=f"(a), "=f"(b) : "l"(v));
}
__device__ __forceinline__ void fma2(ull& d, ull a, ull b) {
    asm("fma.rn.f32x2 %0, %1, %2, %0;" : "+l"(d) : "l"(a), "l"(b));
}
__device__ __forceinline__ float sigmoid_f(float x) {
    float t;
    asm("tanh.approx.f32 %0, %1;" : "=f"(t) : "f"(x * 0.5f));
    return fmaf(t, 0.5f, 0.5f);
}
__device__ __forceinline__ float softplus_f(float x) {
    return fmaxf(x, 0.0f) + __logf(1.0f + __expf(-fabsf(x)));
}
__device__ __forceinline__ void red4(float* p, float4 v) {
    asm volatile("red.global.add.v4.f32 [%0], {%1,%2,%3,%4};"
                 :: "l"(p), "f"(v.x), "f"(v.y), "f"(v.z), "f"(v.w) : "memory");
}
__device__ __forceinline__ void red2(float* p, float a, float b) {
    asm volatile("red.global.add.v2.f32 [%0], {%1,%2};"
                 :: "l"(p), "f"(a), "f"(b) : "memory");
}
__device__ __forceinline__ uint32_t to_tf32(float f) {
    uint32_t r; asm("cvt.rna.tf32.f32 %0, %1;" : "=r"(r) : "f"(f)); return r;
}
__device__ __forceinline__ void mma_tf32(float c[4], uint32_t a0, uint32_t a1,
                                         uint32_t a2, uint32_t a3,
                                         uint32_t b0, uint32_t b1) {
    asm volatile(
        "mma.sync.aligned.m16n8k8.row.col.f32.tf32.tf32.f32 "
        "{%0,%1,%2,%3}, {%4,%5,%6,%7}, {%8,%9}, {%0,%1,%2,%3};"
        : "+f"(c[0]), "+f"(c[1]), "+f"(c[2]), "+f"(c[3])
        : "r"(a0), "r"(a1), "r"(a2), "r"(a3), "r"(b0), "r"(b1));
}

// ---------------- prep: fold weights ----------------
__global__ void prep_kernel(const float* __restrict__ W_emb2, const float* __restrict__ b_emb2,
                            const float* __restrict__ Wf, const float* __restrict__ bf,
                            const float* __restrict__ Ws, const float* __restrict__ bs) {
    int idx = blockIdx.x * blockDim.x + threadIdx.x;
    const int N_WCE = NCV * FE * 2 * HD;
    const int N_BCE = NCV * 2 * HD;
    const int N_WND = NCV * HD * 4 * HD;
    if (idx < N_WCE) {
        int j = idx % (2 * HD);
        int k = (idx / (2 * HD)) % FE;
        int a = idx / (2 * HD * FE);
        const float* Wb = (j < HD) ? Wf : Ws;
        int jj = j & (HD - 1);
        float s = 0.f;
        #pragma unroll 8
        for (int m = 0; m < HD; m++)
            s = fmaf(W_emb2[k * HD + m], Wb[(a * 3 * HD + 2 * HD + m) * HD + jj], s);
        g_Wce[idx] = s;
    } else if (idx < N_WCE + N_BCE) {
        int t = idx - N_WCE;
        int j = t % (2 * HD);
        int a = t / (2 * HD);
        const float* Wb = (j < HD) ? Wf : Ws;
        const float* bb = (j < HD) ? bf : bs;
        int jj = j & (HD - 1);
        float s = bb[a * HD + jj];
        #pragma unroll 8
        for (int m = 0; m < HD; m++)
            s = fmaf(b_emb2[m], Wb[(a * 3 * HD + 2 * HD + m) * HD + jj], s);
        g_bce[t] = s;
    } else if (idx < N_WCE + N_BCE + N_WND) {
        int t = idx - N_WCE - N_BCE;
        int j = t % (4 * HD);
        int m = (t / (4 * HD)) % HD;
        int a = t / (4 * HD * HD);
        int blk = j / HD;                 // 0:f_i 1:s_i 2:f_j 3:s_j
        int jj = j & (HD - 1);
        const float* Wsel = (blk & 1) ? Ws : Wf;
        int roff = (blk >= 2) ? HD : 0;
        g_Wnode[t] = Wsel[(a * 3 * HD + roff + m) * HD + jj];
    }
}

// ---------------- zero counters/stats ----------------
__global__ void zero_kernel() {
    int i = blockIdx.x * blockDim.x + threadIdx.x;
    if (i < NN) { g_deg[i] = 0; g_cursor[i] = 0; }
    if (i < NCV * HD) { g_sum[i] = 0.f; g_sumsq[i] = 0.f; }
    if (i < NG * HD) g_gsum[i] = 0.f;
    if (i < NG) g_gcnt[i] = 0.f;
}

// ---------------- sort by dst ----------------
__global__ void hist_kernel(const int* __restrict__ ei) {
    int e = blockIdx.x * blockDim.x + threadIdx.x;
    if (e < NE) atomicAdd(&g_deg[ei[NE + e]], 1);
}
__global__ void scan1_kernel() {
    __shared__ int s[256];
    int tid = threadIdx.x;
    int i = blockIdx.x * 256 + tid;
    int v = (i < NN) ? g_deg[i] : 0;
    s[tid] = v; __syncthreads();
    #pragma unroll
    for (int off = 1; off < 256; off <<= 1) {
        int t = (tid >= off) ? s[tid - off] : 0;
        __syncthreads();
        s[tid] += t;
        __syncthreads();
    }
    if (i < NN) g_rp[i] = s[tid] - v;
    if (tid == 255) g_bsum[blockIdx.x] = s[255];
}
__global__ void scan2_kernel() {
    __shared__ int s[256];
    int tid = threadIdx.x;
    int v = (tid < NBLK) ? g_bsum[tid] : 0;
    s[tid] = v; __syncthreads();
    #pragma unroll
    for (int off = 1; off < 256; off <<= 1) {
        int t = (tid >= off) ? s[tid - off] : 0;
        __syncthreads();
        s[tid] += t;
        __syncthreads();
    }
    if (tid < NBLK) g_bsum[tid] = s[tid] - v;
}
__global__ void scan3_kernel() {
    int i = blockIdx.x * 256 + threadIdx.x;
    if (i < NN) g_rp[i] += g_bsum[blockIdx.x];
}
__global__ void scatter_kernel(const int* __restrict__ ei) {
    int e = blockIdx.x * blockDim.x + threadIdx.x;
    if (e >= NE) return;
    int d = ei[NE + e];
    int s = ei[e];
    int pos = g_rp[d] + atomicAdd(&g_cursor[d], 1);
    g_perm[pos] = e;
    g_srcp[pos] = s;
    g_dstp[pos] = d;
}
__global__ void permute_ea_kernel(const float* __restrict__ ea) {
    int w = (blockIdx.x * blockDim.x + threadIdx.x) >> 5;
    int lane = threadIdx.x & 31;
    int nw = (gridDim.x * blockDim.x) >> 5;
    for (int row = w; row < NE; row += nw) {
        int e = g_perm[row];
        for (int k = lane; k < FE; k += 32)
            g_eap[(ll)row * FE + k] = ea[(ll)e * FE + k];
    }
}

// ---------------- generic fp32 GEMM with f32x2 inner loop + optional fused BN on A ----
template <int K, int NC, int CT, int RT, int RPT>
__global__ void gemm_bias_kernel(const float* __restrict__ A, const float* __restrict__ B,
                                 const float* __restrict__ bias, float* __restrict__ C,
                                 float* __restrict__ C2, int M, int ldb, int ldc,
                                 const float* __restrict__ bnsum, const float* __restrict__ bnsq,
                                 const float* __restrict__ bngam, const float* __restrict__ bnbet,
                                 int bnrelu, float* __restrict__ wb) {
    constexpr int TR = RT * RPT;
    constexpr int KP = K + 1;
    constexpr int NT = CT * RT;
    extern __shared__ float smem[];
    float* Bs = smem;
    float* As = smem + K * NC;
    float* scl = As + TR * KP;
    float* sft = scl + K;
    int tid = threadIdx.x;
    int tx = tid % CT;
    int ty = tid / CT;
    int c0 = blockIdx.y * NC;
    for (int i = tid; i < K * NC; i += NT) {
        int k = i / NC, c = i - k * NC;
        Bs[i] = B[k * ldb + c0 + c];
    }
    if (bnsum && tid < K) {
        const float invn = 1.0f / (float)M;
        float mu = bnsum[tid] * invn;
        float var = fmaxf(bnsq[tid] * invn - mu * mu, 0.f);
        float sc = rsqrtf(var + BN_EPS) * bngam[tid];
        scl[tid] = sc;
        sft[tid] = bnbet[tid] - mu * sc;
    }
    ull bp[4];
    #pragma unroll
    for (int c = 0; c < 4; c++) {
        float b0 = bias ? bias[c0 + tx * 8 + 2 * c] : 0.f;
        float b1 = bias ? bias[c0 + tx * 8 + 2 * c + 1] : 0.f;
        bp[c] = pack2(b0, b1);
    }
    for (int tile = blockIdx.x; (ll)tile * TR < M; tile += gridDim.x) {
        int row0 = tile * TR;
        __syncthreads();
        for (int i = tid; i < TR * K; i += NT) {
            int r = i / K;
            int k = i - r * K;
            int gr = row0 + r;
            float v = (gr < M) ? A[(ll)gr * K + k] : 0.f;
            if (bnsum) {
                v = fmaf(v, scl[k], sft[k]);
                if (bnrelu) v = fmaxf(v, 0.f);
                if (wb && blockIdx.y == 0 && gr < M) wb[(ll)gr * K + k] = v;
            }
            As[r * KP + k] = v;
        }
        __syncthreads();
        ull acc[RPT][4];
        #pragma unroll
        for (int r = 0; r < RPT; r++)
            #pragma unroll
            for (int c = 0; c < 4; c++) acc[r][c] = bp[c];
        for (int k = 0; k < K; k++) {
            float4 b0 = *reinterpret_cast<const float4*>(&Bs[k * NC + tx * 8]);
            float4 b1 = *reinterpret_cast<const float4*>(&Bs[k * NC + tx * 8 + 4]);
            ull p0 = pack2(b0.x, b0.y), p1 = pack2(b0.z, b0.w);
            ull p2 = pack2(b1.x, b1.y), p3 = pack2(b1.z, b1.w);
            #pragma unroll
            for (int r = 0; r < RPT; r++) {
                float a = As[(ty * RPT + r) * KP + k];
                ull ad = pack2(a, a);
                fma2(acc[r][0], ad, p0);
                fma2(acc[r][1], ad, p1);
                fma2(acc[r][2], ad, p2);
                fma2(acc[r][3], ad, p3);
            }
        }
        #pragma unroll
        for (int r = 0; r < RPT; r++) {
            int gr = row0 + ty * RPT + r;
            if (gr < M) {
                float o[8];
                #pragma unroll
                for (int c = 0; c < 4; c++) unpack2(acc[r][c], o[2 * c], o[2 * c + 1]);
                float* cp = &C[(ll)gr * ldc + c0 + tx * 8];
                *reinterpret_cast<float4*>(cp) = make_float4(o[0], o[1], o[2], o[3]);
                *reinterpret_cast<float4*>(cp + 4) = make_float4(o[4], o[5], o[6], o[7]);
                if (C2) {
                    float* cp2 = &C2[(ll)gr * ldc + c0 + tx * 8];
                    *reinterpret_cast<float4*>(cp2) = make_float4(o[0], o[1], o[2], o[3]);
                    *reinterpret_cast<float4*>(cp2 + 4) = make_float4(o[4], o[5], o[6], o[7]);
                }
            }
        }
    }
}

// ---------------- fused edge kernel: warp-autonomous strips, zero block barriers ----
// Each warp: stage 16 edges' At (private) -> mma -> EW (private, overlaps At) -> message.
// smem: [0,512) bias | [512,25088) Bp | [25088,...) 8 x 8448B per-warp regions.
#define ATW_LD 24
#define SM_BP2 512
#define SM_WR  25088
#define WREG   8448
#define FE_SMEM (SM_WR + 8 * WREG)   // 92672

__global__ __launch_bounds__(256, 2) void fused_edge_kernel(
        float* __restrict__ acc,
        const float* __restrict__ Wce, const float* __restrict__ bce) {
    extern __shared__ char base[];
    float* bias_s = (float*)(base);
    uint2* Bp = (uint2*)(base + SM_BP2);
    int tid = threadIdx.x;
    int lane = tid & 31, wid = tid >> 5;
    int gid = lane >> 2, tig = lane & 3;
    char* wreg = base + SM_WR + wid * WREG;
    uint32_t* Atw = (uint32_t*)wreg;
    float* EWw = (float*)wreg;

    if (tid < 128) bias_s[tid] = bce[tid];
    for (int i = tid; i < 3072; i += 256) {
        int l = i & 31, nt = (i >> 5) & 15, kk = i >> 9;
        int g = l >> 2, t = l & 3;
        int k0 = 8 * kk + t, k1 = k0 + 4, n = 8 * nt + g;
        uint32_t b0 = (k0 < FE) ? to_tf32(Wce[k0 * 128 + n]) : 0u;
        uint32_t b1 = (k1 < FE) ? to_tf32(Wce[k1 * 128 + n]) : 0u;
        Bp[i] = make_uint2(b0, b1);
    }
    __syncthreads();

    const int nstrips = NE / EPW;   // 50000
    int gw = blockIdx.x * 8 + wid;
    int nw = gridDim.x * 8;
    for (int s = gw; s < nstrips; s += nw) {
        int e0 = s * EPW;
        __syncwarp();   // prior message EW reads done before At overwrite
        // stage At[k][r] (linear read from permuted eap)
        for (int i = lane; i < EPW * FE; i += 32) {
            int r = i / FE, k = i - r * FE;
            Atw[k * ATW_LD + r] = to_tf32(g_eap[(ll)e0 * FE + i]);
        }
        for (int i = lane; i < 7 * ATW_LD; i += 32)
            Atw[FE * ATW_LD + i] = 0u;
        int sv = (lane < 16) ? g_srcp[e0 + lane] : g_dstp[e0 + lane - 16];
        __syncwarp();

        // ---- mma: 16 edges x 128 cols ----
        float c[16][4];
        #pragma unroll
        for (int nt = 0; nt < 16; nt++)
            #pragma unroll
            for (int q = 0; q < 4; q++) c[nt][q] = 0.f;
        #pragma unroll
        for (int kk = 0; kk < 6; kk++) {
            uint32_t a0 = Atw[(8 * kk + tig) * ATW_LD + gid];
            uint32_t a1 = Atw[(8 * kk + tig) * ATW_LD + gid + 8];
            uint32_t a2 = Atw[(8 * kk + tig + 4) * ATW_LD + gid];
            uint32_t a3 = Atw[(8 * kk + tig + 4) * ATW_LD + gid + 8];
            #pragma unroll
            for (int nt = 0; nt < 16; nt++) {
                uint2 b = Bp[(kk * 16 + nt) * 32 + lane];
                mma_tf32(c[nt], a0, a1, a2, a3, b.x, b.y);
            }
        }
        __syncwarp();   // At reads done before EW overwrites region

        // ---- EW store (+bias), per-warp private ----
        #pragma unroll
        for (int nt = 0; nt < 16; nt++) {
            float2 bi = *reinterpret_cast<const float2*>(&bias_s[nt * 8 + 2 * tig]);
            *reinterpret_cast<float2*>(&EWw[gid * 132 + nt * 8 + 2 * tig]) =
                make_float2(c[nt][0] + bi.x, c[nt][1] + bi.y);
            *reinterpret_cast<float2*>(&EWw[(gid + 8) * 132 + nt * 8 + 2 * tig]) =
                make_float2(c[nt][2] + bi.x, c[nt][3] + bi.y);
        }
        __syncwarp();

        // ---- message: run-compressed scatter ----
        float2 fj[16], sj[16];
        #pragma unroll
        for (int r = 0; r < 16; r++) {
            int sn = __shfl_sync(0xffffffffu, sv, r);
            fj[r] = *reinterpret_cast<const float2*>(&g_HN[(ll)sn * 256 + 128 + 2 * lane]);
            sj[r] = *reinterpret_cast<const float2*>(&g_HN[(ll)sn * 256 + 192 + 2 * lane]);
        }
        int dprev = -1;
        float fi0 = 0.f, fi1 = 0.f, si0 = 0.f, si1 = 0.f, a0 = 0.f, a1 = 0.f;
        #pragma unroll
        for (int r = 0; r < 16; r++) {
            int d = __shfl_sync(0xffffffffu, sv, 16 + r);
            if (d != dprev) {
                if (dprev >= 0) red2(&acc[(ll)dprev * HD + 2 * lane], a0, a1);
                float2 t0 = *reinterpret_cast<const float2*>(&g_HN[(ll)d * 256 + 2 * lane]);
                float2 t1 = *reinterpret_cast<const float2*>(&g_HN[(ll)d * 256 + 64 + 2 * lane]);
                fi0 = t0.x; fi1 = t0.y; si0 = t1.x; si1 = t1.y;
                a0 = 0.f; a1 = 0.f;
                dprev = d;
            }
            float2 ef = *reinterpret_cast<const float2*>(&EWw[r * 132 + 2 * lane]);
            float2 es = *reinterpret_cast<const float2*>(&EWw[r * 132 + 64 + 2 * lane]);
            a0 += sigmoid_f(ef.x + fi0 + fj[r].x) * softplus_f(es.x + si0 + sj[r].x);
            a1 += sigmoid_f(ef.y + fi1 + fj[r].y) * softplus_f(es.y + si1 + sj[r].y);
        }
        if (dprev >= 0) red2(&acc[(ll)dprev * HD + 2 * lane], a0, a1);
    }
}

// ---------------- BN stats (from buf into slot a) ----------------
__global__ void stats_kernel(int a, const float* __restrict__ buf) {
    __shared__ float s_s[HD], s_q[HD];
    int tid = threadIdx.x;
    if (tid < HD) { s_s[tid] = 0.f; s_q[tid] = 0.f; }
    __syncthreads();
    int col4 = tid & 15;
    float4 ls = make_float4(0.f, 0.f, 0.f, 0.f), lq = ls;
    const float4* acc4 = reinterpret_cast<const float4*>(buf);
    for (int idx4 = blockIdx.x * blockDim.x + tid; idx4 < NN * 16; idx4 += gridDim.x * blockDim.x) {
        float4 v = acc4[idx4];
        ls.x += v.x; lq.x = fmaf(v.x, v.x, lq.x);
        ls.y += v.y; lq.y = fmaf(v.y, v.y, lq.y);
        ls.z += v.z; lq.z = fmaf(v.z, v.z, lq.z);
        ls.w += v.w; lq.w = fmaf(v.w, v.w, lq.w);
    }
    atomicAdd(&s_s[col4 * 4 + 0], ls.x); atomicAdd(&s_q[col4 * 4 + 0], lq.x);
    atomicAdd(&s_s[col4 * 4 + 1], ls.y); atomicAdd(&s_q[col4 * 4 + 1], lq.y);
    atomicAdd(&s_s[col4 * 4 + 2], ls.z); atomicAdd(&s_q[col4 * 4 + 2], lq.z);
    atomicAdd(&s_s[col4 * 4 + 3], ls.w); atomicAdd(&s_q[col4 * 4 + 3], lq.w);
    __syncthreads();
    if (tid < HD) {
        atomicAdd(&g_sum[a * HD + tid], s_s[tid]);
        atomicAdd(&g_sumsq[a * HD + tid], s_q[tid]);
    }
}

// ---------------- final BN + pooling ----------------
__global__ void bn_kernel(const float* __restrict__ gamma, const float* __restrict__ beta,
                          int a, const float* __restrict__ buf,
                          const int* __restrict__ batch) {
    int idx4 = blockIdx.x * blockDim.x + threadIdx.x;
    if (idx4 >= NN * 16) return;
    int col4 = idx4 & 15;
    int node = idx4 >> 4;
    const float invn = 1.0f / (float)NN;
    float4 su = reinterpret_cast<const float4*>(g_sum)[a * 16 + col4];
    float4 sq = reinterpret_cast<const float4*>(g_sumsq)[a * 16 + col4];
    float4 ga = reinterpret_cast<const float4*>(gamma)[col4];
    float4 be = reinterpret_cast<const float4*>(beta)[col4];
    float4 v = reinterpret_cast<const float4*>(buf)[idx4];
    #pragma unroll
    for (int c = 0; c < 4; c++) {
        float mu = (&su.x)[c] * invn;
        float var = fmaxf((&sq.x)[c] * invn - mu * mu, 0.f);
        (&v.x)[c] = ((&v.x)[c] - mu) * rsqrtf(var + BN_EPS) * (&ga.x)[c] + (&be.x)[c];
    }
    int b = batch[node];
    red4(&g_gsum[b * HD + col4 * 4], v);
    if (col4 == 0) atomicAdd(&g_gcnt[b], 1.0f);
}

// ---------------- final MLP ----------------
__global__ void mlp_kernel(const float* __restrict__ W1, const float* __restrict__ b1,
                           const float* __restrict__ W2, const float* __restrict__ b2,
                           const float* __restrict__ Wo, const float* __restrict__ bo,
                           float* __restrict__ out) {
    __shared__ float sW1[HD * HD], sW2[HD * HD], sWo[HD], sb1[HD], sb2[HD];
    int tid = threadIdx.x;
    for (int i = tid; i < HD * HD; i += blockDim.x) { sW1[i] = W1[i]; sW2[i] = W2[i]; }
    if (tid < HD) { sWo[tid] = Wo[tid]; sb1[tid] = b1[tid]; sb2[tid] = b2[tid]; }
    __syncthreads();
    if (tid < NG) {
        float inv = 1.0f / fmaxf(g_gcnt[tid], 1.0f);
        float v[HD], y[HD];
        #pragma unroll
        for (int k = 0; k < HD; k++) v[k] = g_gsum[tid * HD + k] * inv;
        #pragma unroll 1
        for (int j = 0; j < HD; j++) {
            float s = sb1[j];
            #pragma unroll
            for (int k = 0; k < HD; k++) s = fmaf(v[k], sW1[k * HD + j], s);
            y[j] = fmaxf(s, 0.0f) + __logf(1.0f + __expf(-fabsf(s)));
        }
        float o = bo[0];
        #pragma unroll 1
        for (int j = 0; j < HD; j++) {
            float s = sb2[j];
            #pragma unroll
            for (int k = 0; k < HD; k++) s = fmaf(y[k], sW2[k * HD + j], s);
            o = fmaf(fmaxf(s, 0.0f) + __logf(1.0f + __expf(-fabsf(s))), sWo[j], o);
        }
        out[tid] = o;
    }
}

// ---------------- host launcher ----------------
template <int K, int NC, int CT, int RT, int RPT>
static void launch_gemm(const float* A, const float* B, const float* bias, float* C,
                        float* C2, int M, int ldb, int ldc, int nsplit,
                        const float* bnsum, const float* bnsq,
                        const float* bngam, const float* bnbet, int bnrelu, float* wb) {
    constexpr int TR = RT * RPT;
    constexpr int KP = K + 1;
    static_assert(CT * 8 == NC, "col threads x 8 must equal NC");
    size_t sm = (size_t)(K * NC + TR * KP + 2 * K) * sizeof(float);
    if (sm > 48 * 1024) {
        cudaFuncSetAttribute(gemm_bias_kernel<K, NC, CT, RT, RPT>,
                             cudaFuncAttributeMaxDynamicSharedMemorySize, (int)sm);
    }
    dim3 grid((M + TR - 1) / TR, nsplit);
    gemm_bias_kernel<K, NC, CT, RT, RPT><<<grid, CT * RT, sm>>>(
        A, B, bias, C, C2, M, ldb, ldc, bnsum, bnsq, bngam, bnbet, bnrelu, wb);
}

extern "C" void kernel_launch(void* const* d_in, const int* in_sizes, int n_in,
                              void* d_out, int out_size) {
    const float* x         = (const float*)d_in[0];
    const float* edge_attr = (const float*)d_in[1];
    const int*   ei        = (const int*)d_in[2];
    const int*   batch     = (const int*)d_in[3];
    const float* W_emb1    = (const float*)d_in[4];
    const float* b_emb1    = (const float*)d_in[5];
    const float* W_emb2    = (const float*)d_in[6];
    const float* b_emb2    = (const float*)d_in[7];
    const float* Wf        = (const float*)d_in[8];
    const float* bf        = (const float*)d_in[9];
    const float* Ws        = (const float*)d_in[10];
    const float* bs        = (const float*)d_in[11];
    const float* gamma     = (const float*)d_in[12];
    const float* beta      = (const float*)d_in[13];
    const float* W1        = (const float*)d_in[14];
    const float* b1        = (const float*)d_in[15];
    const float* W2        = (const float*)d_in[16];
    const float* b2        = (const float*)d_in[17];
    const float* Wo        = (const float*)d_in[18];
    const float* bo        = (const float*)d_in[19];
    float* out = (float*)d_out;

    float *p_h, *p_acc, *p_Wce, *p_bce, *p_Wnode, *p_HN, *p_sum, *p_sumsq;
    cudaGetSymbolAddress((void**)&p_h, g_h);
    cudaGetSymbolAddress((void**)&p_acc, g_acc);
    cudaGetSymbolAddress((void**)&p_Wce, g_Wce);
    cudaGetSymbolAddress((void**)&p_bce, g_bce);
    cudaGetSymbolAddress((void**)&p_Wnode, g_Wnode);
    cudaGetSymbolAddress((void**)&p_HN, g_HN);
    cudaGetSymbolAddress((void**)&p_sum, g_sum);
    cudaGetSymbolAddress((void**)&p_sumsq, g_sumsq);

    // fold weights + zero counters/stats
    prep_kernel<<<255, 256>>>(W_emb2, b_emb2, Wf, bf, Ws, bs);
    zero_kernel<<<NBLK, 256>>>();

    // sort edges by dst (counting sort) + permute edge_attr (linear staging reads)
    hist_kernel<<<(NE + 255) / 256, 256>>>(ei);
    scan1_kernel<<<NBLK, 256>>>();
    scan2_kernel<<<1, 256>>>();
    scan3_kernel<<<NBLK, 256>>>();
    scatter_kernel<<<(NE + 255) / 256, 256>>>(ei);
    permute_ea_kernel<<<1600, 256>>>(edge_attr);

    // h0 = x @ W_emb1 + b_emb1, dual-stored to g_h and g_acc
    launch_gemm<FX, HD, 8, 32, 4>(x, W_emb1, b_emb1, p_h, p_acc, NN, HD, HD, 1,
                                  nullptr, nullptr, nullptr, nullptr, 0, nullptr);

    cudaFuncSetAttribute(fused_edge_kernel,
                         cudaFuncAttributeMaxDynamicSharedMemorySize, FE_SMEM);

    // ping-pong raw accumulator: L0->g_acc, L1->g_h, L2->g_acc
    float* rawbuf[3] = { p_acc, p_h, p_acc };
    float* srcbuf[3] = { p_h, p_acc, p_h };

    for (int a = 0; a < NCV; a++) {
        const float* bnsum = (a == 0) ? nullptr : p_sum + (a - 1) * HD;
        const float* bnsq  = (a == 0) ? nullptr : p_sumsq + (a - 1) * HD;
        const float* bngam = (a == 0) ? nullptr : gamma + (a - 1) * HD;
        const float* bnbet = (a == 0) ? nullptr : beta + (a - 1) * HD;
        float* wb = (a == 0) ? nullptr : rawbuf[a];
        // HN = BN?(src) @ Wnode[a], 4 column chunks of 64
        launch_gemm<HD, HD, 8, 32, 4>(srcbuf[a], p_Wnode + (ll)a * HD * 4 * HD,
                                      nullptr, p_HN, nullptr, NN, 4 * HD, 4 * HD, 4,
                                      bnsum, bnsq, bngam, bnbet, 1, wb);
        fused_edge_kernel<<<296, 256, FE_SMEM>>>(rawbuf[a],
                                                 p_Wce + a * FE * 2 * HD,
                                                 p_bce + a * 2 * HD);
        stats_kernel<<<296, 256>>>(a, rawbuf[a]);
    }

    // final BN (no relu) + pooling from rawbuf[2]
    bn_kernel<<<(NN * 16 + 255) / 256, 256>>>(gamma + 2 * HD, beta + 2 * HD, 2,
                                              rawbuf[2], batch);

    mlp_kernel<<<1, 128>>>(W1, b1, W2, b2, Wo, bo, out);
}

// round 12
// speedup vs baseline: 1.3887x; 1.1509x over previous
#include <cuda_runtime.h>
#include <math.h>
#include <stdint.h>

#define NN 50000      // nodes
#define NE 800000     // edges
#define NG 128        // graphs
#define FX 92         // node feature dim
#define FE 41         // edge feature dim
#define HD 64         // hidden
#define NCV 3         // conv layers
#define BN_EPS 1e-5f
#define NBLK 196      // scan blocks
#define EPW 16        // edges per warp-strip

typedef unsigned long long ull;
typedef long long ll;

// ---------------- device scratch ----------------
__device__ float g_h[NN * HD];
__device__ float g_acc[NN * HD];
__device__ float g_HN[NN * 4 * HD];                   // [N,256]: [f_i|s_i|f_j|s_j]
__device__ float g_Wce[NCV * FE * 2 * HD];
__device__ float g_bce[NCV * 2 * HD];
__device__ float g_Wnode[NCV * HD * 4 * HD];
__device__ float g_sum[NCV * HD];
__device__ float g_sumsq[NCV * HD];
__device__ float g_gsum[NG * HD];
__device__ float g_gcnt[NG];
// sort-by-dst machinery
__device__ int   g_deg[NN];
__device__ int   g_cursor[NN];
__device__ int   g_rp[NN];
__device__ int   g_bsum[256];
__device__ int   g_perm[NE];
__device__ int   g_srcp[NE];
__device__ int   g_dstp[NE];
__device__ float g_eap[(ll)NE * FE];   // permuted edge_attr

// ---------------- helpers ----------------
__device__ __forceinline__ ull pack2(float a, float b) {
    ull r; asm("mov.b64 %0, {%1, %2};" : "=l"(r) : "f"(a), "f"(b)); return r;
}
__device__ __forceinline__ void unpack2(ull v, float& a, float& b) {
    asm("mov.b64 {%0, %1}, %2;" : "=f"(a), "=f"(b) : "l"(v));
}
__device__ __forceinline__ void fma2(ull& d, ull a, ull b) {
    asm("fma.rn.f32x2 %0, %1, %2, %0;" : "+l"(d) : "l"(a), "l"(b));
}
__device__ __forceinline__ float sigmoid_f(float x) {
    float t;
    asm("tanh.approx.f32 %0, %1;" : "=f"(t) : "f"(x * 0.5f));
    return fmaf(t, 0.5f, 0.5f);
}
__device__ __forceinline__ float softplus_f(float x) {
    return fmaxf(x, 0.0f) + __logf(1.0f + __expf(-fabsf(x)));
}
__device__ __forceinline__ void red4(float* p, float4 v) {
    asm volatile("red.global.add.v4.f32 [%0], {%1,%2,%3,%4};"
                 :: "l"(p), "f"(v.x), "f"(v.y), "f"(v.z), "f"(v.w) : "memory");
}
__device__ __forceinline__ void red2(float* p, float a, float b) {
    asm volatile("red.global.add.v2.f32 [%0], {%1,%2};"
                 :: "l"(p), "f"(a), "f"(b) : "memory");
}
__device__ __forceinline__ uint32_t to_tf32(float f) {
    uint32_t r; asm("cvt.rna.tf32.f32 %0, %1;" : "=r"(r) : "f"(f)); return r;
}
__device__ __forceinline__ void mma_tf32(float c[4], uint32_t a0, uint32_t a1,
                                         uint32_t a2, uint32_t a3,
                                         uint32_t b0, uint32_t b1) {
    asm volatile(
        "mma.sync.aligned.m16n8k8.row.col.f32.tf32.tf32.f32 "
        "{%0,%1,%2,%3}, {%4,%5,%6,%7}, {%8,%9}, {%0,%1,%2,%3};"
        : "+f"(c[0]), "+f"(c[1]), "+f"(c[2]), "+f"(c[3])
        : "r"(a0), "r"(a1), "r"(a2), "r"(a3), "r"(b0), "r"(b1));
}

// ---------------- prep: fold weights ----------------
__global__ void prep_kernel(const float* __restrict__ W_emb2, const float* __restrict__ b_emb2,
                            const float* __restrict__ Wf, const float* __restrict__ bf,
                            const float* __restrict__ Ws, const float* __restrict__ bs) {
    int idx = blockIdx.x * blockDim.x + threadIdx.x;
    const int N_WCE = NCV * FE * 2 * HD;
    const int N_BCE = NCV * 2 * HD;
    const int N_WND = NCV * HD * 4 * HD;
    if (idx < N_WCE) {
        int j = idx % (2 * HD);
        int k = (idx / (2 * HD)) % FE;
        int a = idx / (2 * HD * FE);
        const float* Wb = (j < HD) ? Wf : Ws;
        int jj = j & (HD - 1);
        float s = 0.f;
        #pragma unroll 8
        for (int m = 0; m < HD; m++)
            s = fmaf(W_emb2[k * HD + m], Wb[(a * 3 * HD + 2 * HD + m) * HD + jj], s);
        g_Wce[idx] = s;
    } else if (idx < N_WCE + N_BCE) {
        int t = idx - N_WCE;
        int j = t % (2 * HD);
        int a = t / (2 * HD);
        const float* Wb = (j < HD) ? Wf : Ws;
        const float* bb = (j < HD) ? bf : bs;
        int jj = j & (HD - 1);
        float s = bb[a * HD + jj];
        #pragma unroll 8
        for (int m = 0; m < HD; m++)
            s = fmaf(b_emb2[m], Wb[(a * 3 * HD + 2 * HD + m) * HD + jj], s);
        g_bce[t] = s;
    } else if (idx < N_WCE + N_BCE + N_WND) {
        int t = idx - N_WCE - N_BCE;
        int j = t % (4 * HD);
        int m = (t / (4 * HD)) % HD;
        int a = t / (4 * HD * HD);
        int blk = j / HD;                 // 0:f_i 1:s_i 2:f_j 3:s_j
        int jj = j & (HD - 1);
        const float* Wsel = (blk & 1) ? Ws : Wf;
        int roff = (blk >= 2) ? HD : 0;
        g_Wnode[t] = Wsel[(a * 3 * HD + roff + m) * HD + jj];
    }
}

// ---------------- zero counters/stats ----------------
__global__ void zero_kernel() {
    int i = blockIdx.x * blockDim.x + threadIdx.x;
    if (i < NN) { g_deg[i] = 0; g_cursor[i] = 0; }
    if (i < NCV * HD) { g_sum[i] = 0.f; g_sumsq[i] = 0.f; }
    if (i < NG * HD) g_gsum[i] = 0.f;
    if (i < NG) g_gcnt[i] = 0.f;
}

// ---------------- sort by dst ----------------
__global__ void hist_kernel(const int* __restrict__ ei) {
    int e = blockIdx.x * blockDim.x + threadIdx.x;
    if (e < NE) atomicAdd(&g_deg[ei[NE + e]], 1);
}
__global__ void scan1_kernel() {
    __shared__ int s[256];
    int tid = threadIdx.x;
    int i = blockIdx.x * 256 + tid;
    int v = (i < NN) ? g_deg[i] : 0;
    s[tid] = v; __syncthreads();
    #pragma unroll
    for (int off = 1; off < 256; off <<= 1) {
        int t = (tid >= off) ? s[tid - off] : 0;
        __syncthreads();
        s[tid] += t;
        __syncthreads();
    }
    if (i < NN) g_rp[i] = s[tid] - v;
    if (tid == 255) g_bsum[blockIdx.x] = s[255];
}
__global__ void scan2_kernel() {
    __shared__ int s[256];
    int tid = threadIdx.x;
    int v = (tid < NBLK) ? g_bsum[tid] : 0;
    s[tid] = v; __syncthreads();
    #pragma unroll
    for (int off = 1; off < 256; off <<= 1) {
        int t = (tid >= off) ? s[tid - off] : 0;
        __syncthreads();
        s[tid] += t;
        __syncthreads();
    }
    if (tid < NBLK) g_bsum[tid] = s[tid] - v;
}
__global__ void scan3_kernel() {
    int i = blockIdx.x * 256 + threadIdx.x;
    if (i < NN) g_rp[i] += g_bsum[blockIdx.x];
}
__global__ void scatter_kernel(const int* __restrict__ ei) {
    int e = blockIdx.x * blockDim.x + threadIdx.x;
    if (e >= NE) return;
    int d = ei[NE + e];
    int s = ei[e];
    int pos = g_rp[d] + atomicAdd(&g_cursor[d], 1);
    g_perm[pos] = e;
    g_srcp[pos] = s;
    g_dstp[pos] = d;
}
__global__ void permute_ea_kernel(const float* __restrict__ ea) {
    int w = (blockIdx.x * blockDim.x + threadIdx.x) >> 5;
    int lane = threadIdx.x & 31;
    int nw = (gridDim.x * blockDim.x) >> 5;
    for (int row = w; row < NE; row += nw) {
        int e = g_perm[row];
        for (int k = lane; k < FE; k += 32)
            g_eap[(ll)row * FE + k] = ea[(ll)e * FE + k];
    }
}

// ---------------- fp32 GEMM (embedding only) with f32x2 inner loop ----------------
template <int K, int NC, int CT, int RT, int RPT>
__global__ void gemm_bias_kernel(const float* __restrict__ A, const float* __restrict__ B,
                                 const float* __restrict__ bias, float* __restrict__ C,
                                 float* __restrict__ C2, int M, int ldb, int ldc) {
    constexpr int TR = RT * RPT;
    constexpr int KP = K + 1;
    constexpr int NT = CT * RT;
    extern __shared__ float smem[];
    float* Bs = smem;
    float* As = smem + K * NC;
    int tid = threadIdx.x;
    int tx = tid % CT;
    int ty = tid / CT;
    int c0 = blockIdx.y * NC;
    for (int i = tid; i < K * NC; i += NT) {
        int k = i / NC, c = i - k * NC;
        Bs[i] = B[k * ldb + c0 + c];
    }
    ull bp[4];
    #pragma unroll
    for (int c = 0; c < 4; c++) {
        float b0 = bias ? bias[c0 + tx * 8 + 2 * c] : 0.f;
        float b1 = bias ? bias[c0 + tx * 8 + 2 * c + 1] : 0.f;
        bp[c] = pack2(b0, b1);
    }
    for (int tile = blockIdx.x; (ll)tile * TR < M; tile += gridDim.x) {
        int row0 = tile * TR;
        __syncthreads();
        for (int i = tid; i < TR * K; i += NT) {
            int r = i / K;
            int k = i - r * K;
            int gr = row0 + r;
            As[r * KP + k] = (gr < M) ? A[(ll)gr * K + k] : 0.f;
        }
        __syncthreads();
        ull acc[RPT][4];
        #pragma unroll
        for (int r = 0; r < RPT; r++)
            #pragma unroll
            for (int c = 0; c < 4; c++) acc[r][c] = bp[c];
        for (int k = 0; k < K; k++) {
            float4 b0 = *reinterpret_cast<const float4*>(&Bs[k * NC + tx * 8]);
            float4 b1 = *reinterpret_cast<const float4*>(&Bs[k * NC + tx * 8 + 4]);
            ull p0 = pack2(b0.x, b0.y), p1 = pack2(b0.z, b0.w);
            ull p2 = pack2(b1.x, b1.y), p3 = pack2(b1.z, b1.w);
            #pragma unroll
            for (int r = 0; r < RPT; r++) {
                float a = As[(ty * RPT + r) * KP + k];
                ull ad = pack2(a, a);
                fma2(acc[r][0], ad, p0);
                fma2(acc[r][1], ad, p1);
                fma2(acc[r][2], ad, p2);
                fma2(acc[r][3], ad, p3);
            }
        }
        #pragma unroll
        for (int r = 0; r < RPT; r++) {
            int gr = row0 + ty * RPT + r;
            if (gr < M) {
                float o[8];
                #pragma unroll
                for (int c = 0; c < 4; c++) unpack2(acc[r][c], o[2 * c], o[2 * c + 1]);
                float* cp = &C[(ll)gr * ldc + c0 + tx * 8];
                *reinterpret_cast<float4*>(cp) = make_float4(o[0], o[1], o[2], o[3]);
                *reinterpret_cast<float4*>(cp + 4) = make_float4(o[4], o[5], o[6], o[7]);
                if (C2) {
                    float* cp2 = &C2[(ll)gr * ldc + c0 + tx * 8];
                    *reinterpret_cast<float4*>(cp2) = make_float4(o[0], o[1], o[2], o[3]);
                    *reinterpret_cast<float4*>(cp2 + 4) = make_float4(o[4], o[5], o[6], o[7]);
                }
            }
        }
    }
}

// ---------------- node GEMM: mma.sync tf32, warp-autonomous, fused BN ----------------
// HN[50k,256] = BN?(src)[50k,64] @ Wn[64,256]; normalized rows optionally -> wb.
// 512 threads, 16 warps; warp strips of 16 rows; K=64 = 8 k-steps exactly.
// smem: [0,512) scl/sft | [512,66048) Bp (8192 uint2) | 16 x 6144B Atw regions.
#define ND_ATLD 24
#define ND_SMBP 512
#define ND_SMWR 66048
#define ND_WREG 6144
#define ND_SMEM (ND_SMWR + 16 * ND_WREG)   // 164352

__global__ __launch_bounds__(512, 1) void node_mma_kernel(
        const float* __restrict__ src, const float* __restrict__ Wn,
        float* __restrict__ HN, float* __restrict__ wb,
        const float* __restrict__ bnsum, const float* __restrict__ bnsq,
        const float* __restrict__ bngam, const float* __restrict__ bnbet) {
    extern __shared__ char base[];
    float* scl = (float*)base;
    float* sft = scl + HD;
    uint2* Bp = (uint2*)(base + ND_SMBP);
    int tid = threadIdx.x;
    int lane = tid & 31, wid = tid >> 5;
    int gid = lane >> 2, tig = lane & 3;
    uint32_t* Atw = (uint32_t*)(base + ND_SMWR + wid * ND_WREG);
    int dobn = (bnsum != nullptr);

    if (dobn && tid < HD) {
        const float invn = 1.0f / (float)NN;
        float mu = bnsum[tid] * invn;
        float var = fmaxf(bnsq[tid] * invn - mu * mu, 0.f);
        float sc = rsqrtf(var + BN_EPS) * bngam[tid];
        scl[tid] = sc;
        sft[tid] = bnbet[tid] - mu * sc;
    }
    // prepack B fragments: Bp[(kk*32+nt)*32+lane] = {Wn[8kk+tig][8nt+gid], Wn[8kk+tig+4][8nt+gid]}
    for (int i = tid; i < 8192; i += 512) {
        int l = i & 31, nt = (i >> 5) & 31, kk = i >> 10;
        int g = l >> 2, t = l & 3;
        Bp[i] = make_uint2(to_tf32(Wn[(8 * kk + t) * 256 + 8 * nt + g]),
                           to_tf32(Wn[(8 * kk + t + 4) * 256 + 8 * nt + g]));
    }
    __syncthreads();

    const int nstrips = NN / EPW;   // 3125
    int gw = blockIdx.x * 16 + wid;
    int nw = gridDim.x * 16;
    for (int s = gw; s < nstrips; s += nw) {
        int row0 = s * EPW;
        __syncwarp();   // prior strip's Atw reads done
        // stage A^T with fused BN+relu and write-back
        for (int i = lane; i < EPW * HD; i += 32) {
            int r = i >> 6, k = i & 63;
            int gr = row0 + r;
            float v = src[(ll)gr * HD + k];
            if (dobn) {
                v = fmaxf(fmaf(v, scl[k], sft[k]), 0.f);
                wb[(ll)gr * HD + k] = v;
            }
            Atw[k * ND_ATLD + r] = to_tf32(v);
        }
        __syncwarp();
        #pragma unroll
        for (int h = 0; h < 2; h++) {
            float c[16][4];
            #pragma unroll
            for (int nt = 0; nt < 16; nt++)
                #pragma unroll
                for (int q = 0; q < 4; q++) c[nt][q] = 0.f;
            #pragma unroll
            for (int kk = 0; kk < 8; kk++) {
                uint32_t a0 = Atw[(8 * kk + tig) * ND_ATLD + gid];
                uint32_t a1 = Atw[(8 * kk + tig) * ND_ATLD + gid + 8];
                uint32_t a2 = Atw[(8 * kk + tig + 4) * ND_ATLD + gid];
                uint32_t a3 = Atw[(8 * kk + tig + 4) * ND_ATLD + gid + 8];
                #pragma unroll
                for (int nt = 0; nt < 16; nt++) {
                    uint2 b = Bp[(kk * 32 + h * 16 + nt) * 32 + lane];
                    mma_tf32(c[nt], a0, a1, a2, a3, b.x, b.y);
                }
            }
            #pragma unroll
            for (int nt = 0; nt < 16; nt++) {
                int col = h * 128 + nt * 8 + 2 * tig;
                *reinterpret_cast<float2*>(&HN[(ll)(row0 + gid) * 256 + col]) =
                    make_float2(c[nt][0], c[nt][1]);
                *reinterpret_cast<float2*>(&HN[(ll)(row0 + gid + 8) * 256 + col]) =
                    make_float2(c[nt][2], c[nt][3]);
            }
        }
    }
}

// ---------------- fused edge kernel: warp-autonomous strips, zero block barriers ----
#define ATW_LD 24
#define SM_BP2 512
#define SM_WR  25088
#define WREG   8448
#define FE_SMEM (SM_WR + 8 * WREG)   // 92672

__global__ __launch_bounds__(256, 2) void fused_edge_kernel(
        float* __restrict__ acc,
        const float* __restrict__ Wce, const float* __restrict__ bce) {
    extern __shared__ char base[];
    float* bias_s = (float*)(base);
    uint2* Bp = (uint2*)(base + SM_BP2);
    int tid = threadIdx.x;
    int lane = tid & 31, wid = tid >> 5;
    int gid = lane >> 2, tig = lane & 3;
    char* wreg = base + SM_WR + wid * WREG;
    uint32_t* Atw = (uint32_t*)wreg;
    float* EWw = (float*)wreg;

    if (tid < 128) bias_s[tid] = bce[tid];
    for (int i = tid; i < 3072; i += 256) {
        int l = i & 31, nt = (i >> 5) & 15, kk = i >> 9;
        int g = l >> 2, t = l & 3;
        int k0 = 8 * kk + t, k1 = k0 + 4, n = 8 * nt + g;
        uint32_t b0 = (k0 < FE) ? to_tf32(Wce[k0 * 128 + n]) : 0u;
        uint32_t b1 = (k1 < FE) ? to_tf32(Wce[k1 * 128 + n]) : 0u;
        Bp[i] = make_uint2(b0, b1);
    }
    __syncthreads();

    const int nstrips = NE / EPW;   // 50000
    int gw = blockIdx.x * 8 + wid;
    int nw = gridDim.x * 8;
    for (int s = gw; s < nstrips; s += nw) {
        int e0 = s * EPW;
        __syncwarp();
        for (int i = lane; i < EPW * FE; i += 32) {
            int r = i / FE, k = i - r * FE;
            Atw[k * ATW_LD + r] = to_tf32(g_eap[(ll)e0 * FE + i]);
        }
        for (int i = lane; i < 7 * ATW_LD; i += 32)
            Atw[FE * ATW_LD + i] = 0u;
        int sv = (lane < 16) ? g_srcp[e0 + lane] : g_dstp[e0 + lane - 16];
        __syncwarp();

        float c[16][4];
        #pragma unroll
        for (int nt = 0; nt < 16; nt++)
            #pragma unroll
            for (int q = 0; q < 4; q++) c[nt][q] = 0.f;
        #pragma unroll
        for (int kk = 0; kk < 6; kk++) {
            uint32_t a0 = Atw[(8 * kk + tig) * ATW_LD + gid];
            uint32_t a1 = Atw[(8 * kk + tig) * ATW_LD + gid + 8];
            uint32_t a2 = Atw[(8 * kk + tig + 4) * ATW_LD + gid];
            uint32_t a3 = Atw[(8 * kk + tig + 4) * ATW_LD + gid + 8];
            #pragma unroll
            for (int nt = 0; nt < 16; nt++) {
                uint2 b = Bp[(kk * 16 + nt) * 32 + lane];
                mma_tf32(c[nt], a0, a1, a2, a3, b.x, b.y);
            }
        }
        __syncwarp();

        #pragma unroll
        for (int nt = 0; nt < 16; nt++) {
            float2 bi = *reinterpret_cast<const float2*>(&bias_s[nt * 8 + 2 * tig]);
            *reinterpret_cast<float2*>(&EWw[gid * 132 + nt * 8 + 2 * tig]) =
                make_float2(c[nt][0] + bi.x, c[nt][1] + bi.y);
            *reinterpret_cast<float2*>(&EWw[(gid + 8) * 132 + nt * 8 + 2 * tig]) =
                make_float2(c[nt][2] + bi.x, c[nt][3] + bi.y);
        }
        __syncwarp();

        float2 fj[16], sj[16];
        #pragma unroll
        for (int r = 0; r < 16; r++) {
            int sn = __shfl_sync(0xffffffffu, sv, r);
            fj[r] = *reinterpret_cast<const float2*>(&g_HN[(ll)sn * 256 + 128 + 2 * lane]);
            sj[r] = *reinterpret_cast<const float2*>(&g_HN[(ll)sn * 256 + 192 + 2 * lane]);
        }
        int dprev = -1;
        float fi0 = 0.f, fi1 = 0.f, si0 = 0.f, si1 = 0.f, a0 = 0.f, a1 = 0.f;
        #pragma unroll
        for (int r = 0; r < 16; r++) {
            int d = __shfl_sync(0xffffffffu, sv, 16 + r);
            if (d != dprev) {
                if (dprev >= 0) red2(&acc[(ll)dprev * HD + 2 * lane], a0, a1);
                float2 t0 = *reinterpret_cast<const float2*>(&g_HN[(ll)d * 256 + 2 * lane]);
                float2 t1 = *reinterpret_cast<const float2*>(&g_HN[(ll)d * 256 + 64 + 2 * lane]);
                fi0 = t0.x; fi1 = t0.y; si0 = t1.x; si1 = t1.y;
                a0 = 0.f; a1 = 0.f;
                dprev = d;
            }
            float2 ef = *reinterpret_cast<const float2*>(&EWw[r * 132 + 2 * lane]);
            float2 es = *reinterpret_cast<const float2*>(&EWw[r * 132 + 64 + 2 * lane]);
            a0 += sigmoid_f(ef.x + fi0 + fj[r].x) * softplus_f(es.x + si0 + sj[r].x);
            a1 += sigmoid_f(ef.y + fi1 + fj[r].y) * softplus_f(es.y + si1 + sj[r].y);
        }
        if (dprev >= 0) red2(&acc[(ll)dprev * HD + 2 * lane], a0, a1);
    }
}

// ---------------- BN stats (from buf into slot a) ----------------
__global__ void stats_kernel(int a, const float* __restrict__ buf) {
    __shared__ float s_s[HD], s_q[HD];
    int tid = threadIdx.x;
    if (tid < HD) { s_s[tid] = 0.f; s_q[tid] = 0.f; }
    __syncthreads();
    int col4 = tid & 15;
    float4 ls = make_float4(0.f, 0.f, 0.f, 0.f), lq = ls;
    const float4* acc4 = reinterpret_cast<const float4*>(buf);
    for (int idx4 = blockIdx.x * blockDim.x + tid; idx4 < NN * 16; idx4 += gridDim.x * blockDim.x) {
        float4 v = acc4[idx4];
        ls.x += v.x; lq.x = fmaf(v.x, v.x, lq.x);
        ls.y += v.y; lq.y = fmaf(v.y, v.y, lq.y);
        ls.z += v.z; lq.z = fmaf(v.z, v.z, lq.z);
        ls.w += v.w; lq.w = fmaf(v.w, v.w, lq.w);
    }
    atomicAdd(&s_s[col4 * 4 + 0], ls.x); atomicAdd(&s_q[col4 * 4 + 0], lq.x);
    atomicAdd(&s_s[col4 * 4 + 1], ls.y); atomicAdd(&s_q[col4 * 4 + 1], lq.y);
    atomicAdd(&s_s[col4 * 4 + 2], ls.z); atomicAdd(&s_q[col4 * 4 + 2], lq.z);
    atomicAdd(&s_s[col4 * 4 + 3], ls.w); atomicAdd(&s_q[col4 * 4 + 3], lq.w);
    __syncthreads();
    if (tid < HD) {
        atomicAdd(&g_sum[a * HD + tid], s_s[tid]);
        atomicAdd(&g_sumsq[a * HD + tid], s_q[tid]);
    }
}

// ---------------- final BN + pooling ----------------
__global__ void bn_kernel(const float* __restrict__ gamma, const float* __restrict__ beta,
                          int a, const float* __restrict__ buf,
                          const int* __restrict__ batch) {
    int idx4 = blockIdx.x * blockDim.x + threadIdx.x;
    if (idx4 >= NN * 16) return;
    int col4 = idx4 & 15;
    int node = idx4 >> 4;
    const float invn = 1.0f / (float)NN;
    float4 su = reinterpret_cast<const float4*>(g_sum)[a * 16 + col4];
    float4 sq = reinterpret_cast<const float4*>(g_sumsq)[a * 16 + col4];
    float4 ga = reinterpret_cast<const float4*>(gamma)[col4];
    float4 be = reinterpret_cast<const float4*>(beta)[col4];
    float4 v = reinterpret_cast<const float4*>(buf)[idx4];
    #pragma unroll
    for (int c = 0; c < 4; c++) {
        float mu = (&su.x)[c] * invn;
        float var = fmaxf((&sq.x)[c] * invn - mu * mu, 0.f);
        (&v.x)[c] = ((&v.x)[c] - mu) * rsqrtf(var + BN_EPS) * (&ga.x)[c] + (&be.x)[c];
    }
    int b = batch[node];
    red4(&g_gsum[b * HD + col4 * 4], v);
    if (col4 == 0) atomicAdd(&g_gcnt[b], 1.0f);
}

// ---------------- final MLP ----------------
__global__ void mlp_kernel(const float* __restrict__ W1, const float* __restrict__ b1,
                           const float* __restrict__ W2, const float* __restrict__ b2,
                           const float* __restrict__ Wo, const float* __restrict__ bo,
                           float* __restrict__ out) {
    __shared__ float sW1[HD * HD], sW2[HD * HD], sWo[HD], sb1[HD], sb2[HD];
    int tid = threadIdx.x;
    for (int i = tid; i < HD * HD; i += blockDim.x) { sW1[i] = W1[i]; sW2[i] = W2[i]; }
    if (tid < HD) { sWo[tid] = Wo[tid]; sb1[tid] = b1[tid]; sb2[tid] = b2[tid]; }
    __syncthreads();
    if (tid < NG) {
        float inv = 1.0f / fmaxf(g_gcnt[tid], 1.0f);
        float v[HD], y[HD];
        #pragma unroll
        for (int k = 0; k < HD; k++) v[k] = g_gsum[tid * HD + k] * inv;
        #pragma unroll 1
        for (int j = 0; j < HD; j++) {
            float s = sb1[j];
            #pragma unroll
            for (int k = 0; k < HD; k++) s = fmaf(v[k], sW1[k * HD + j], s);
            y[j] = fmaxf(s, 0.0f) + __logf(1.0f + __expf(-fabsf(s)));
        }
        float o = bo[0];
        #pragma unroll 1
        for (int j = 0; j < HD; j++) {
            float s = sb2[j];
            #pragma unroll
            for (int k = 0; k < HD; k++) s = fmaf(y[k], sW2[k * HD + j], s);
            o = fmaf(fmaxf(s, 0.0f) + __logf(1.0f + __expf(-fabsf(s))), sWo[j], o);
        }
        out[tid] = o;
    }
}

// ---------------- host launcher ----------------
template <int K, int NC, int CT, int RT, int RPT>
static void launch_gemm(const float* A, const float* B, const float* bias, float* C,
                        float* C2, int M, int ldb, int ldc, int nsplit) {
    constexpr int TR = RT * RPT;
    constexpr int KP = K + 1;
    static_assert(CT * 8 == NC, "col threads x 8 must equal NC");
    size_t sm = (size_t)(K * NC + TR * KP) * sizeof(float);
    if (sm > 48 * 1024) {
        cudaFuncSetAttribute(gemm_bias_kernel<K, NC, CT, RT, RPT>,
                             cudaFuncAttributeMaxDynamicSharedMemorySize, (int)sm);
    }
    dim3 grid((M + TR - 1) / TR, nsplit);
    gemm_bias_kernel<K, NC, CT, RT, RPT><<<grid, CT * RT, sm>>>(A, B, bias, C, C2, M, ldb, ldc);
}

extern "C" void kernel_launch(void* const* d_in, const int* in_sizes, int n_in,
                              void* d_out, int out_size) {
    const float* x         = (const float*)d_in[0];
    const float* edge_attr = (const float*)d_in[1];
    const int*   ei        = (const int*)d_in[2];
    const int*   batch     = (const int*)d_in[3];
    const float* W_emb1    = (const float*)d_in[4];
    const float* b_emb1    = (const float*)d_in[5];
    const float* W_emb2    = (const float*)d_in[6];
    const float* b_emb2    = (const float*)d_in[7];
    const float* Wf        = (const float*)d_in[8];
    const float* bf        = (const float*)d_in[9];
    const float* Ws        = (const float*)d_in[10];
    const float* bs        = (const float*)d_in[11];
    const float* gamma     = (const float*)d_in[12];
    const float* beta      = (const float*)d_in[13];
    const float* W1        = (const float*)d_in[14];
    const float* b1        = (const float*)d_in[15];
    const float* W2        = (const float*)d_in[16];
    const float* b2        = (const float*)d_in[17];
    const float* Wo        = (const float*)d_in[18];
    const float* bo        = (const float*)d_in[19];
    float* out = (float*)d_out;

    float *p_h, *p_acc, *p_Wce, *p_bce, *p_Wnode, *p_HN, *p_sum, *p_sumsq;
    cudaGetSymbolAddress((void**)&p_h, g_h);
    cudaGetSymbolAddress((void**)&p_acc, g_acc);
    cudaGetSymbolAddress((void**)&p_Wce, g_Wce);
    cudaGetSymbolAddress((void**)&p_bce, g_bce);
    cudaGetSymbolAddress((void**)&p_Wnode, g_Wnode);
    cudaGetSymbolAddress((void**)&p_HN, g_HN);
    cudaGetSymbolAddress((void**)&p_sum, g_sum);
    cudaGetSymbolAddress((void**)&p_sumsq, g_sumsq);

    // fold weights + zero counters/stats
    prep_kernel<<<255, 256>>>(W_emb2, b_emb2, Wf, bf, Ws, bs);
    zero_kernel<<<NBLK, 256>>>();

    // sort edges by dst (counting sort) + permute edge_attr
    hist_kernel<<<(NE + 255) / 256, 256>>>(ei);
    scan1_kernel<<<NBLK, 256>>>();
    scan2_kernel<<<1, 256>>>();
    scan3_kernel<<<NBLK, 256>>>();
    scatter_kernel<<<(NE + 255) / 256, 256>>>(ei);
    permute_ea_kernel<<<1600, 256>>>(edge_attr);

    // h0 = x @ W_emb1 + b_emb1, dual-stored to g_h and g_acc
    launch_gemm<FX, HD, 8, 32, 4>(x, W_emb1, b_emb1, p_h, p_acc, NN, HD, HD, 1);

    cudaFuncSetAttribute(fused_edge_kernel,
                         cudaFuncAttributeMaxDynamicSharedMemorySize, FE_SMEM);
    cudaFuncSetAttribute(node_mma_kernel,
                         cudaFuncAttributeMaxDynamicSharedMemorySize, ND_SMEM);

    // ping-pong raw accumulator: L0->g_acc, L1->g_h, L2->g_acc
    float* rawbuf[3] = { p_acc, p_h, p_acc };
    float* srcbuf[3] = { p_h, p_acc, p_h };

    for (int a = 0; a < NCV; a++) {
        const float* bnsum = (a == 0) ? nullptr : p_sum + (a - 1) * HD;
        const float* bnsq  = (a == 0) ? nullptr : p_sumsq + (a - 1) * HD;
        const float* bngam = (a == 0) ? nullptr : gamma + (a - 1) * HD;
        const float* bnbet = (a == 0) ? nullptr : beta + (a - 1) * HD;
        float* wb = (a == 0) ? nullptr : rawbuf[a];
        // HN = BN?(src) @ Wnode[a] via tensor cores; normalized h -> wb
        node_mma_kernel<<<148, 512, ND_SMEM>>>(srcbuf[a],
                                               p_Wnode + (ll)a * HD * 4 * HD,
                                               p_HN, wb, bnsum, bnsq, bngam, bnbet);
        fused_edge_kernel<<<296, 256, FE_SMEM>>>(rawbuf[a],
                                                 p_Wce + a * FE * 2 * HD,
                                                 p_bce + a * 2 * HD);
        stats_kernel<<<296, 256>>>(a, rawbuf[a]);
    }

    // final BN (no relu) + pooling from rawbuf[2]
    bn_kernel<<<(NN * 16 + 255) / 256, 256>>>(gamma + 2 * HD, beta + 2 * HD, 2,
                                              rawbuf[2], batch);

    mlp_kernel<<<1, 128>>>(W1, b1, W2, b2, Wo, bo, out);
}

// round 13
// speedup vs baseline: 1.4303x; 1.0300x over previous
#include <cuda_runtime.h>
#include <math.h>
#include <stdint.h>

#define NN 50000      // nodes
#define NE 800000     // edges
#define NG 128        // graphs
#define FX 92         // node feature dim
#define FE 41         // edge feature dim
#define HD 64         // hidden
#define NCV 3         // conv layers
#define BN_EPS 1e-5f
#define NBLK 196      // scan blocks
#define EPW 16        // rows/edges per warp-strip

typedef unsigned long long ull;
typedef long long ll;

// ---------------- device scratch ----------------
__device__ float g_h[NN * HD];
__device__ float g_acc[NN * HD];
__device__ float g_HN[NN * 4 * HD];                   // [N,256]: [f_i|s_i|f_j|s_j]
__device__ float g_Wce[NCV * FE * 2 * HD];
__device__ float g_bce[NCV * 2 * HD];
__device__ float g_Wnode[NCV * HD * 4 * HD];
__device__ float g_sum[NCV * HD];
__device__ float g_sumsq[NCV * HD];
__device__ float g_gsum[NG * HD];
__device__ float g_gcnt[NG];
// sort-by-dst machinery
__device__ int   g_deg[NN];
__device__ int   g_cursor[NN];
__device__ int   g_rp[NN];
__device__ int   g_bsum[256];
__device__ int   g_srcp[NE];
__device__ int   g_dstp[NE];
__device__ float g_eap[(ll)NE * FE];   // permuted edge_attr (row-major, sorted order)

// ---------------- helpers ----------------
__device__ __forceinline__ float sigmoid_f(float x) {
    float t;
    asm("tanh.approx.f32 %0, %1;" : "=f"(t) : "f"(x * 0.5f));
    return fmaf(t, 0.5f, 0.5f);
}
__device__ __forceinline__ float softplus_f(float x) {
    return fmaxf(x, 0.0f) + __logf(1.0f + __expf(-fabsf(x)));
}
__device__ __forceinline__ void red4(float* p, float4 v) {
    asm volatile("red.global.add.v4.f32 [%0], {%1,%2,%3,%4};"
                 :: "l"(p), "f"(v.x), "f"(v.y), "f"(v.z), "f"(v.w) : "memory");
}
__device__ __forceinline__ void red2(float* p, float a, float b) {
    asm volatile("red.global.add.v2.f32 [%0], {%1,%2};"
                 :: "l"(p), "f"(a), "f"(b) : "memory");
}
__device__ __forceinline__ uint32_t to_tf32(float f) {
    uint32_t r; asm("cvt.rna.tf32.f32 %0, %1;" : "=r"(r) : "f"(f)); return r;
}
__device__ __forceinline__ void mma_tf32(float c[4], uint32_t a0, uint32_t a1,
                                         uint32_t a2, uint32_t a3,
                                         uint32_t b0, uint32_t b1) {
    asm volatile(
        "mma.sync.aligned.m16n8k8.row.col.f32.tf32.tf32.f32 "
        "{%0,%1,%2,%3}, {%4,%5,%6,%7}, {%8,%9}, {%0,%1,%2,%3};"
        : "+f"(c[0]), "+f"(c[1]), "+f"(c[2]), "+f"(c[3])
        : "r"(a0), "r"(a1), "r"(a2), "r"(a3), "r"(b0), "r"(b1));
}

// ---------------- prep: fold weights + zero counters/stats ----------------
__global__ void prep_kernel(const float* __restrict__ W_emb2, const float* __restrict__ b_emb2,
                            const float* __restrict__ Wf, const float* __restrict__ bf,
                            const float* __restrict__ Ws, const float* __restrict__ bs) {
    int idx = blockIdx.x * blockDim.x + threadIdx.x;
    const int N_WCE = NCV * FE * 2 * HD;
    const int N_BCE = NCV * 2 * HD;
    const int N_WND = NCV * HD * 4 * HD;
    // zeroing (merged)
    if (idx < NN) { g_deg[idx] = 0; g_cursor[idx] = 0; }
    if (idx < NCV * HD) { g_sum[idx] = 0.f; g_sumsq[idx] = 0.f; }
    if (idx < NG * HD) g_gsum[idx] = 0.f;
    if (idx < NG) g_gcnt[idx] = 0.f;
    if (idx < N_WCE) {
        int j = idx % (2 * HD);
        int k = (idx / (2 * HD)) % FE;
        int a = idx / (2 * HD * FE);
        const float* Wb = (j < HD) ? Wf : Ws;
        int jj = j & (HD - 1);
        float s = 0.f;
        #pragma unroll 8
        for (int m = 0; m < HD; m++)
            s = fmaf(W_emb2[k * HD + m], Wb[(a * 3 * HD + 2 * HD + m) * HD + jj], s);
        g_Wce[idx] = s;
    } else if (idx < N_WCE + N_BCE) {
        int t = idx - N_WCE;
        int j = t % (2 * HD);
        int a = t / (2 * HD);
        const float* Wb = (j < HD) ? Wf : Ws;
        const float* bb = (j < HD) ? bf : bs;
        int jj = j & (HD - 1);
        float s = bb[a * HD + jj];
        #pragma unroll 8
        for (int m = 0; m < HD; m++)
            s = fmaf(b_emb2[m], Wb[(a * 3 * HD + 2 * HD + m) * HD + jj], s);
        g_bce[t] = s;
    } else if (idx < N_WCE + N_BCE + N_WND) {
        int t = idx - N_WCE - N_BCE;
        int j = t % (4 * HD);
        int m = (t / (4 * HD)) % HD;
        int a = t / (4 * HD * HD);
        int blk = j / HD;                 // 0:f_i 1:s_i 2:f_j 3:s_j
        int jj = j & (HD - 1);
        const float* Wsel = (blk & 1) ? Ws : Wf;
        int roff = (blk >= 2) ? HD : 0;
        g_Wnode[t] = Wsel[(a * 3 * HD + roff + m) * HD + jj];
    }
}

// ---------------- sort by dst ----------------
__global__ void hist_kernel(const int* __restrict__ ei) {
    int e = blockIdx.x * blockDim.x + threadIdx.x;
    if (e < NE) atomicAdd(&g_deg[ei[NE + e]], 1);
}
__global__ void scan1_kernel() {
    __shared__ int s[256];
    int tid = threadIdx.x;
    int i = blockIdx.x * 256 + tid;
    int v = (i < NN) ? g_deg[i] : 0;
    s[tid] = v; __syncthreads();
    #pragma unroll
    for (int off = 1; off < 256; off <<= 1) {
        int t = (tid >= off) ? s[tid - off] : 0;
        __syncthreads();
        s[tid] += t;
        __syncthreads();
    }
    if (i < NN) g_rp[i] = s[tid] - v;
    if (tid == 255) g_bsum[blockIdx.x] = s[255];
}
__global__ void scan2_kernel() {
    __shared__ int s[256];
    int tid = threadIdx.x;
    int v = (tid < NBLK) ? g_bsum[tid] : 0;
    s[tid] = v; __syncthreads();
    #pragma unroll
    for (int off = 1; off < 256; off <<= 1) {
        int t = (tid >= off) ? s[tid - off] : 0;
        __syncthreads();
        s[tid] += t;
        __syncthreads();
    }
    if (tid < NBLK) g_bsum[tid] = s[tid] - v;
}
__global__ void scan3_kernel() {
    int i = blockIdx.x * 256 + threadIdx.x;
    if (i < NN) g_rp[i] += g_bsum[blockIdx.x];
}
// merged scatter + edge_attr permute: warp per edge
__global__ void scatter_perm_kernel(const int* __restrict__ ei, const float* __restrict__ ea) {
    int w = (blockIdx.x * blockDim.x + threadIdx.x) >> 5;
    int lane = threadIdx.x & 31;
    int nw = (gridDim.x * blockDim.x) >> 5;
    for (int e = w; e < NE; e += nw) {
        int pos = 0;
        if (lane == 0) {
            int d = ei[NE + e];
            int s = ei[e];
            pos = g_rp[d] + atomicAdd(&g_cursor[d], 1);
            g_srcp[pos] = s;
            g_dstp[pos] = d;
        }
        pos = __shfl_sync(0xffffffffu, pos, 0);
        for (int k = lane; k < FE; k += 32)
            g_eap[(ll)pos * FE + k] = ea[(ll)e * FE + k];
    }
}

// ---------------- embedding GEMM: mma.sync tf32, warp-autonomous ----------------
// h0[50k,64] = x[50k,92] @ W_emb1[92,64] + b; dual-store to g_h and g_acc.
// K padded 92->96 (12 k-steps). 512 threads, 16 warps; strips of 16 rows.
#define EM_ATLD 24
#define EM_SMBP 512
#define EM_SMWR (EM_SMBP + 3072 * 8)          // 25088
#define EM_WREG 9216                           // 96*24*4
#define EM_SMEM (EM_SMWR + 16 * EM_WREG)       // 172544

__global__ __launch_bounds__(512, 1) void emb_mma_kernel(
        const float* __restrict__ x, const float* __restrict__ W, const float* __restrict__ b) {
    extern __shared__ char base[];
    float* bias_s = (float*)base;
    uint2* Bp = (uint2*)(base + EM_SMBP);
    int tid = threadIdx.x;
    int lane = tid & 31, wid = tid >> 5;
    int gid = lane >> 2, tig = lane & 3;
    uint32_t* Atw = (uint32_t*)(base + EM_SMWR + wid * EM_WREG);

    if (tid < HD) bias_s[tid] = b[tid];
    // prepack B fragments: 12 ksteps x 8 ntiles
    for (int i = tid; i < 3072; i += 512) {
        int l = i & 31, nt = (i >> 5) & 7, kk = i >> 8;
        int g = l >> 2, t = l & 3;
        int k0 = 8 * kk + t, k1 = k0 + 4;
        uint32_t b0 = (k0 < FX) ? to_tf32(W[k0 * HD + 8 * nt + g]) : 0u;
        uint32_t b1 = (k1 < FX) ? to_tf32(W[k1 * HD + 8 * nt + g]) : 0u;
        Bp[i] = make_uint2(b0, b1);
    }
    // zero padding rows 92..95 of own region (never overwritten)
    for (int i = lane; i < 4 * EM_ATLD; i += 32) Atw[FX * EM_ATLD + i] = 0u;
    __syncthreads();

    const int nstrips = NN / EPW;   // 3125
    int gw = blockIdx.x * 16 + wid;
    int nw = gridDim.x * 16;
    for (int s = gw; s < nstrips; s += nw) {
        int row0 = s * EPW;
        __syncwarp();
        // stage A^T: 16 rows x 92 = 368 float4 (aligned)
        const float4* s4 = reinterpret_cast<const float4*>(&x[(ll)row0 * FX]);
        #pragma unroll
        for (int j = 0; j < 12; j++) {
            int i4 = lane + 32 * j;
            if (i4 < 368) {
                float4 v = s4[i4];
                int r = __float2int_rd((i4 + 0.5f) * (1.0f / 23.0f));
                int k0 = (i4 - 23 * r) * 4;
                Atw[(k0 + 0) * EM_ATLD + r] = to_tf32(v.x);
                Atw[(k0 + 1) * EM_ATLD + r] = to_tf32(v.y);
                Atw[(k0 + 2) * EM_ATLD + r] = to_tf32(v.z);
                Atw[(k0 + 3) * EM_ATLD + r] = to_tf32(v.w);
            }
        }
        __syncwarp();
        float c[8][4];
        #pragma unroll
        for (int nt = 0; nt < 8; nt++)
            #pragma unroll
            for (int q = 0; q < 4; q++) c[nt][q] = 0.f;
        #pragma unroll
        for (int kk = 0; kk < 12; kk++) {
            uint32_t a0 = Atw[(8 * kk + tig) * EM_ATLD + gid];
            uint32_t a1 = Atw[(8 * kk + tig) * EM_ATLD + gid + 8];
            uint32_t a2 = Atw[(8 * kk + tig + 4) * EM_ATLD + gid];
            uint32_t a3 = Atw[(8 * kk + tig + 4) * EM_ATLD + gid + 8];
            #pragma unroll
            for (int nt = 0; nt < 8; nt++) {
                uint2 bb = Bp[(kk * 8 + nt) * 32 + lane];
                mma_tf32(c[nt], a0, a1, a2, a3, bb.x, bb.y);
            }
        }
        #pragma unroll
        for (int nt = 0; nt < 8; nt++) {
            int col = nt * 8 + 2 * tig;
            float2 bi = *reinterpret_cast<const float2*>(&bias_s[col]);
            float2 v0 = make_float2(c[nt][0] + bi.x, c[nt][1] + bi.y);
            float2 v1 = make_float2(c[nt][2] + bi.x, c[nt][3] + bi.y);
            *reinterpret_cast<float2*>(&g_h[(ll)(row0 + gid) * HD + col]) = v0;
            *reinterpret_cast<float2*>(&g_acc[(ll)(row0 + gid) * HD + col]) = v0;
            *reinterpret_cast<float2*>(&g_h[(ll)(row0 + gid + 8) * HD + col]) = v1;
            *reinterpret_cast<float2*>(&g_acc[(ll)(row0 + gid + 8) * HD + col]) = v1;
        }
    }
}

// ---------------- node GEMM: mma.sync tf32, warp-autonomous, fused BN ----------------
#define ND_ATLD 24
#define ND_SMBP 512
#define ND_SMWR 66048
#define ND_WREG 6144
#define ND_SMEM (ND_SMWR + 16 * ND_WREG)   // 164352

__global__ __launch_bounds__(512, 1) void node_mma_kernel(
        const float* __restrict__ src, const float* __restrict__ Wn,
        float* __restrict__ HN, float* __restrict__ wb,
        const float* __restrict__ bnsum, const float* __restrict__ bnsq,
        const float* __restrict__ bngam, const float* __restrict__ bnbet) {
    extern __shared__ char base[];
    float* scl = (float*)base;
    float* sft = scl + HD;
    uint2* Bp = (uint2*)(base + ND_SMBP);
    int tid = threadIdx.x;
    int lane = tid & 31, wid = tid >> 5;
    int gid = lane >> 2, tig = lane & 3;
    uint32_t* Atw = (uint32_t*)(base + ND_SMWR + wid * ND_WREG);
    int dobn = (bnsum != nullptr);

    if (dobn && tid < HD) {
        const float invn = 1.0f / (float)NN;
        float mu = bnsum[tid] * invn;
        float var = fmaxf(bnsq[tid] * invn - mu * mu, 0.f);
        float sc = rsqrtf(var + BN_EPS) * bngam[tid];
        scl[tid] = sc;
        sft[tid] = bnbet[tid] - mu * sc;
    }
    for (int i = tid; i < 8192; i += 512) {
        int l = i & 31, nt = (i >> 5) & 31, kk = i >> 10;
        int g = l >> 2, t = l & 3;
        Bp[i] = make_uint2(to_tf32(Wn[(8 * kk + t) * 256 + 8 * nt + g]),
                           to_tf32(Wn[(8 * kk + t + 4) * 256 + 8 * nt + g]));
    }
    __syncthreads();

    const int nstrips = NN / EPW;   // 3125
    int gw = blockIdx.x * 16 + wid;
    int nw = gridDim.x * 16;
    for (int s = gw; s < nstrips; s += nw) {
        int row0 = s * EPW;
        __syncwarp();
        for (int i = lane; i < EPW * HD; i += 32) {
            int r = i >> 6, k = i & 63;
            int gr = row0 + r;
            float v = src[(ll)gr * HD + k];
            if (dobn) {
                v = fmaxf(fmaf(v, scl[k], sft[k]), 0.f);
                wb[(ll)gr * HD + k] = v;
            }
            Atw[k * ND_ATLD + r] = to_tf32(v);
        }
        __syncwarp();
        #pragma unroll
        for (int h = 0; h < 2; h++) {
            float c[16][4];
            #pragma unroll
            for (int nt = 0; nt < 16; nt++)
                #pragma unroll
                for (int q = 0; q < 4; q++) c[nt][q] = 0.f;
            #pragma unroll
            for (int kk = 0; kk < 8; kk++) {
                uint32_t a0 = Atw[(8 * kk + tig) * ND_ATLD + gid];
                uint32_t a1 = Atw[(8 * kk + tig) * ND_ATLD + gid + 8];
                uint32_t a2 = Atw[(8 * kk + tig + 4) * ND_ATLD + gid];
                uint32_t a3 = Atw[(8 * kk + tig + 4) * ND_ATLD + gid + 8];
                #pragma unroll
                for (int nt = 0; nt < 16; nt++) {
                    uint2 b = Bp[(kk * 32 + h * 16 + nt) * 32 + lane];
                    mma_tf32(c[nt], a0, a1, a2, a3, b.x, b.y);
                }
            }
            #pragma unroll
            for (int nt = 0; nt < 16; nt++) {
                int col = h * 128 + nt * 8 + 2 * tig;
                *reinterpret_cast<float2*>(&HN[(ll)(row0 + gid) * 256 + col]) =
                    make_float2(c[nt][0], c[nt][1]);
                *reinterpret_cast<float2*>(&HN[(ll)(row0 + gid + 8) * 256 + col]) =
                    make_float2(c[nt][2], c[nt][3]);
            }
        }
    }
}

// ---------------- fused edge kernel: warp-autonomous strips ----------------
#define ATW_LD 24
#define SM_BP2 512
#define SM_WR  25088
#define WREG   8448
#define FE_SMEM (SM_WR + 8 * WREG)   // 92672

__global__ __launch_bounds__(256, 2) void fused_edge_kernel(
        float* __restrict__ acc,
        const float* __restrict__ Wce, const float* __restrict__ bce) {
    extern __shared__ char base[];
    float* bias_s = (float*)(base);
    uint2* Bp = (uint2*)(base + SM_BP2);
    int tid = threadIdx.x;
    int lane = tid & 31, wid = tid >> 5;
    int gid = lane >> 2, tig = lane & 3;
    char* wreg = base + SM_WR + wid * WREG;
    uint32_t* Atw = (uint32_t*)wreg;
    float* EWw = (float*)wreg;

    if (tid < 128) bias_s[tid] = bce[tid];
    for (int i = tid; i < 3072; i += 256) {
        int l = i & 31, nt = (i >> 5) & 15, kk = i >> 9;
        int g = l >> 2, t = l & 3;
        int k0 = 8 * kk + t, k1 = k0 + 4, n = 8 * nt + g;
        uint32_t b0 = (k0 < FE) ? to_tf32(Wce[k0 * 128 + n]) : 0u;
        uint32_t b1 = (k1 < FE) ? to_tf32(Wce[k1 * 128 + n]) : 0u;
        Bp[i] = make_uint2(b0, b1);
    }
    __syncthreads();

    const int nstrips = NE / EPW;   // 50000
    int gw = blockIdx.x * 8 + wid;
    int nw = gridDim.x * 8;
    for (int s = gw; s < nstrips; s += nw) {
        int e0 = s * EPW;
        __syncwarp();
        // stage A^T: 656 floats = 164 float4 (aligned), div-by-41 via float trick
        const float4* s4 = reinterpret_cast<const float4*>(&g_eap[(ll)e0 * FE]);
        #pragma unroll
        for (int j = 0; j < 6; j++) {
            int i4 = lane + 32 * j;
            if (i4 < 164) {
                float4 v = s4[i4];
                int ib = 4 * i4;
                #pragma unroll
                for (int q = 0; q < 4; q++) {
                    int i = ib + q;
                    int r = __float2int_rd((i + 0.5f) * (1.0f / 41.0f));
                    int k = i - 41 * r;
                    Atw[k * ATW_LD + r] = to_tf32((&v.x)[q]);
                }
            }
        }
        for (int i = lane; i < 7 * ATW_LD; i += 32)
            Atw[FE * ATW_LD + i] = 0u;
        int sv = (lane < 16) ? g_srcp[e0 + lane] : g_dstp[e0 + lane - 16];
        __syncwarp();

        float c[16][4];
        #pragma unroll
        for (int nt = 0; nt < 16; nt++)
            #pragma unroll
            for (int q = 0; q < 4; q++) c[nt][q] = 0.f;
        #pragma unroll
        for (int kk = 0; kk < 6; kk++) {
            uint32_t a0 = Atw[(8 * kk + tig) * ATW_LD + gid];
            uint32_t a1 = Atw[(8 * kk + tig) * ATW_LD + gid + 8];
            uint32_t a2 = Atw[(8 * kk + tig + 4) * ATW_LD + gid];
            uint32_t a3 = Atw[(8 * kk + tig + 4) * ATW_LD + gid + 8];
            #pragma unroll
            for (int nt = 0; nt < 16; nt++) {
                uint2 b = Bp[(kk * 16 + nt) * 32 + lane];
                mma_tf32(c[nt], a0, a1, a2, a3, b.x, b.y);
            }
        }
        __syncwarp();

        #pragma unroll
        for (int nt = 0; nt < 16; nt++) {
            float2 bi = *reinterpret_cast<const float2*>(&bias_s[nt * 8 + 2 * tig]);
            *reinterpret_cast<float2*>(&EWw[gid * 132 + nt * 8 + 2 * tig]) =
                make_float2(c[nt][0] + bi.x, c[nt][1] + bi.y);
            *reinterpret_cast<float2*>(&EWw[(gid + 8) * 132 + nt * 8 + 2 * tig]) =
                make_float2(c[nt][2] + bi.x, c[nt][3] + bi.y);
        }
        __syncwarp();

        float2 fj[16], sj[16];
        #pragma unroll
        for (int r = 0; r < 16; r++) {
            int sn = __shfl_sync(0xffffffffu, sv, r);
            fj[r] = *reinterpret_cast<const float2*>(&g_HN[(ll)sn * 256 + 128 + 2 * lane]);
            sj[r] = *reinterpret_cast<const float2*>(&g_HN[(ll)sn * 256 + 192 + 2 * lane]);
        }
        int dprev = -1;
        float fi0 = 0.f, fi1 = 0.f, si0 = 0.f, si1 = 0.f, a0 = 0.f, a1 = 0.f;
        #pragma unroll
        for (int r = 0; r < 16; r++) {
            int d = __shfl_sync(0xffffffffu, sv, 16 + r);
            if (d != dprev) {
                if (dprev >= 0) red2(&acc[(ll)dprev * HD + 2 * lane], a0, a1);
                float2 t0 = *reinterpret_cast<const float2*>(&g_HN[(ll)d * 256 + 2 * lane]);
                float2 t1 = *reinterpret_cast<const float2*>(&g_HN[(ll)d * 256 + 64 + 2 * lane]);
                fi0 = t0.x; fi1 = t0.y; si0 = t1.x; si1 = t1.y;
                a0 = 0.f; a1 = 0.f;
                dprev = d;
            }
            float2 ef = *reinterpret_cast<const float2*>(&EWw[r * 132 + 2 * lane]);
            float2 es = *reinterpret_cast<const float2*>(&EWw[r * 132 + 64 + 2 * lane]);
            a0 += sigmoid_f(ef.x + fi0 + fj[r].x) * softplus_f(es.x + si0 + sj[r].x);
            a1 += sigmoid_f(ef.y + fi1 + fj[r].y) * softplus_f(es.y + si1 + sj[r].y);
        }
        if (dprev >= 0) red2(&acc[(ll)dprev * HD + 2 * lane], a0, a1);
    }
}

// ---------------- BN stats ----------------
__global__ void stats_kernel(int a, const float* __restrict__ buf) {
    __shared__ float s_s[HD], s_q[HD];
    int tid = threadIdx.x;
    if (tid < HD) { s_s[tid] = 0.f; s_q[tid] = 0.f; }
    __syncthreads();
    int col4 = tid & 15;
    float4 ls = make_float4(0.f, 0.f, 0.f, 0.f), lq = ls;
    const float4* acc4 = reinterpret_cast<const float4*>(buf);
    for (int idx4 = blockIdx.x * blockDim.x + tid; idx4 < NN * 16; idx4 += gridDim.x * blockDim.x) {
        float4 v = acc4[idx4];
        ls.x += v.x; lq.x = fmaf(v.x, v.x, lq.x);
        ls.y += v.y; lq.y = fmaf(v.y, v.y, lq.y);
        ls.z += v.z; lq.z = fmaf(v.z, v.z, lq.z);
        ls.w += v.w; lq.w = fmaf(v.w, v.w, lq.w);
    }
    atomicAdd(&s_s[col4 * 4 + 0], ls.x); atomicAdd(&s_q[col4 * 4 + 0], lq.x);
    atomicAdd(&s_s[col4 * 4 + 1], ls.y); atomicAdd(&s_q[col4 * 4 + 1], lq.y);
    atomicAdd(&s_s[col4 * 4 + 2], ls.z); atomicAdd(&s_q[col4 * 4 + 2], lq.z);
    atomicAdd(&s_s[col4 * 4 + 3], ls.w); atomicAdd(&s_q[col4 * 4 + 3], lq.w);
    __syncthreads();
    if (tid < HD) {
        atomicAdd(&g_sum[a * HD + tid], s_s[tid]);
        atomicAdd(&g_sumsq[a * HD + tid], s_q[tid]);
    }
}

// ---------------- final BN + pooling ----------------
__global__ void bn_kernel(const float* __restrict__ gamma, const float* __restrict__ beta,
                          int a, const float* __restrict__ buf,
                          const int* __restrict__ batch) {
    int idx4 = blockIdx.x * blockDim.x + threadIdx.x;
    if (idx4 >= NN * 16) return;
    int col4 = idx4 & 15;
    int node = idx4 >> 4;
    const float invn = 1.0f / (float)NN;
    float4 su = reinterpret_cast<const float4*>(g_sum)[a * 16 + col4];
    float4 sq = reinterpret_cast<const float4*>(g_sumsq)[a * 16 + col4];
    float4 ga = reinterpret_cast<const float4*>(gamma)[col4];
    float4 be = reinterpret_cast<const float4*>(beta)[col4];
    float4 v = reinterpret_cast<const float4*>(buf)[idx4];
    #pragma unroll
    for (int c = 0; c < 4; c++) {
        float mu = (&su.x)[c] * invn;
        float var = fmaxf((&sq.x)[c] * invn - mu * mu, 0.f);
        (&v.x)[c] = ((&v.x)[c] - mu) * rsqrtf(var + BN_EPS) * (&ga.x)[c] + (&be.x)[c];
    }
    int b = batch[node];
    red4(&g_gsum[b * HD + col4 * 4], v);
    if (col4 == 0) atomicAdd(&g_gcnt[b], 1.0f);
}

// ---------------- final MLP ----------------
__global__ void mlp_kernel(const float* __restrict__ W1, const float* __restrict__ b1,
                           const float* __restrict__ W2, const float* __restrict__ b2,
                           const float* __restrict__ Wo, const float* __restrict__ bo,
                           float* __restrict__ out) {
    __shared__ float sW1[HD * HD], sW2[HD * HD], sWo[HD], sb1[HD], sb2[HD];
    int tid = threadIdx.x;
    for (int i = tid; i < HD * HD; i += blockDim.x) { sW1[i] = W1[i]; sW2[i] = W2[i]; }
    if (tid < HD) { sWo[tid] = Wo[tid]; sb1[tid] = b1[tid]; sb2[tid] = b2[tid]; }
    __syncthreads();
    if (tid < NG) {
        float inv = 1.0f / fmaxf(g_gcnt[tid], 1.0f);
        float v[HD], y[HD];
        #pragma unroll
        for (int k = 0; k < HD; k++) v[k] = g_gsum[tid * HD + k] * inv;
        #pragma unroll 1
        for (int j = 0; j < HD; j++) {
            float s = sb1[j];
            #pragma unroll
            for (int k = 0; k < HD; k++) s = fmaf(v[k], sW1[k * HD + j], s);
            y[j] = fmaxf(s, 0.0f) + __logf(1.0f + __expf(-fabsf(s)));
        }
        float o = bo[0];
        #pragma unroll 1
        for (int j = 0; j < HD; j++) {
            float s = sb2[j];
            #pragma unroll
            for (int k = 0; k < HD; k++) s = fmaf(y[k], sW2[k * HD + j], s);
            o = fmaf(fmaxf(s, 0.0f) + __logf(1.0f + __expf(-fabsf(s))), sWo[j], o);
        }
        out[tid] = o;
    }
}

extern "C" void kernel_launch(void* const* d_in, const int* in_sizes, int n_in,
                              void* d_out, int out_size) {
    const float* x         = (const float*)d_in[0];
    const float* edge_attr = (const float*)d_in[1];
    const int*   ei        = (const int*)d_in[2];
    const int*   batch     = (const int*)d_in[3];
    const float* W_emb1    = (const float*)d_in[4];
    const float* b_emb1    = (const float*)d_in[5];
    const float* W_emb2    = (const float*)d_in[6];
    const float* b_emb2    = (const float*)d_in[7];
    const float* Wf        = (const float*)d_in[8];
    const float* bf        = (const float*)d_in[9];
    const float* Ws        = (const float*)d_in[10];
    const float* bs        = (const float*)d_in[11];
    const float* gamma     = (const float*)d_in[12];
    const float* beta      = (const float*)d_in[13];
    const float* W1        = (const float*)d_in[14];
    const float* b1        = (const float*)d_in[15];
    const float* W2        = (const float*)d_in[16];
    const float* b2        = (const float*)d_in[17];
    const float* Wo        = (const float*)d_in[18];
    const float* bo        = (const float*)d_in[19];
    float* out = (float*)d_out;

    float *p_h, *p_acc, *p_Wce, *p_bce, *p_Wnode, *p_HN, *p_sum, *p_sumsq;
    cudaGetSymbolAddress((void**)&p_h, g_h);
    cudaGetSymbolAddress((void**)&p_acc, g_acc);
    cudaGetSymbolAddress((void**)&p_Wce, g_Wce);
    cudaGetSymbolAddress((void**)&p_bce, g_bce);
    cudaGetSymbolAddress((void**)&p_Wnode, g_Wnode);
    cudaGetSymbolAddress((void**)&p_HN, g_HN);
    cudaGetSymbolAddress((void**)&p_sum, g_sum);
    cudaGetSymbolAddress((void**)&p_sumsq, g_sumsq);

    // fold weights + zero counters/stats (merged)
    prep_kernel<<<255, 256>>>(W_emb2, b_emb2, Wf, bf, Ws, bs);

    // sort edges by dst + permute edge_attr (merged scatter)
    hist_kernel<<<(NE + 255) / 256, 256>>>(ei);
    scan1_kernel<<<NBLK, 256>>>();
    scan2_kernel<<<1, 256>>>();
    scan3_kernel<<<NBLK, 256>>>();
    scatter_perm_kernel<<<3200, 256>>>(ei, edge_attr);

    cudaFuncSetAttribute(emb_mma_kernel,
                         cudaFuncAttributeMaxDynamicSharedMemorySize, EM_SMEM);
    cudaFuncSetAttribute(node_mma_kernel,
                         cudaFuncAttributeMaxDynamicSharedMemorySize, ND_SMEM);
    cudaFuncSetAttribute(fused_edge_kernel,
                         cudaFuncAttributeMaxDynamicSharedMemorySize, FE_SMEM);

    // h0 = x @ W_emb1 + b_emb1, dual-stored to g_h and g_acc (tensor path)
    emb_mma_kernel<<<148, 512, EM_SMEM>>>(x, W_emb1, b_emb1);

    // ping-pong raw accumulator: L0->g_acc, L1->g_h, L2->g_acc
    float* rawbuf[3] = { p_acc, p_h, p_acc };
    float* srcbuf[3] = { p_h, p_acc, p_h };

    for (int a = 0; a < NCV; a++) {
        const float* bnsum = (a == 0) ? nullptr : p_sum + (a - 1) * HD;
        const float* bnsq  = (a == 0) ? nullptr : p_sumsq + (a - 1) * HD;
        const float* bngam = (a == 0) ? nullptr : gamma + (a - 1) * HD;
        const float* bnbet = (a == 0) ? nullptr : beta + (a - 1) * HD;
        float* wb = (a == 0) ? nullptr : rawbuf[a];
        node_mma_kernel<<<148, 512, ND_SMEM>>>(srcbuf[a],
                                               p_Wnode + (ll)a * HD * 4 * HD,
                                               p_HN, wb, bnsum, bnsq, bngam, bnbet);
        fused_edge_kernel<<<296, 256, FE_SMEM>>>(rawbuf[a],
                                                 p_Wce + a * FE * 2 * HD,
                                                 p_bce + a * 2 * HD);
        stats_kernel<<<296, 256>>>(a, rawbuf[a]);
    }

    // final BN (no relu) + pooling from rawbuf[2]
    bn_kernel<<<(NN * 16 + 255) / 256, 256>>>(gamma + 2 * HD, beta + 2 * HD, 2,
                                              rawbuf[2], batch);

    mlp_kernel<<<1, 128>>>(W1, b1, W2, b2, Wo, bo, out);
}